// round 10
// baseline (speedup 1.0000x reference)
#include <cuda_runtime.h>
#include <cuda_bf16.h>
#include <math.h>
#include <stdint.h>

#define BB 2
#define TT 1024
#define CC 512
#define HH 8
#define DD 64
#define LL 4
#define VV 32000

typedef __nv_bfloat16 bf16;

// ---------------- scratch (no cudaMalloc allowed) ----------------
__device__ float g_x   [BB*TT*CC];          // residual stream (fp32)
__device__ float g_qkv [BB*TT*3*CC];        // fused qkv (fp32)
__device__ bf16  g_h_hi[BB*TT*CC],  g_h_lo[BB*TT*CC];     // LN out split
__device__ bf16  g_y_hi[BB*TT*CC],  g_y_lo[BB*TT*CC];     // attn out split
__device__ bf16  g_h1_hi[BB*TT*4*CC], g_h1_lo[BB*TT*4*CC];// MLP hidden split
// packed weights (transposed to [N][K], split hi/lo)
__device__ bf16 g_wqkv_hi[LL*3*CC*CC], g_wqkv_lo[LL*3*CC*CC];
__device__ bf16 g_wo_hi  [LL*CC*CC],   g_wo_lo  [LL*CC*CC];
__device__ bf16 g_w1_hi  [LL*4*CC*CC], g_w1_lo  [LL*4*CC*CC];
__device__ bf16 g_w2_hi  [LL*4*CC*CC], g_w2_lo  [LL*4*CC*CC];
__device__ bf16 g_wh_hi  [VV*CC],      g_wh_lo  [VV*CC];
__device__ float g_bqkv [LL*3*CC];

// ---------------------------------------------------------------------------
// Weight pack: out_hi/lo[n][k] = split(W[k][n]).  64x64 tile, vectorized:
// float4 loads, smem transpose, 16B (8xbf16) stores.
// ---------------------------------------------------------------------------
__global__ __launch_bounds__(256) void pack_w(const float* __restrict__ W,
                                              bf16* __restrict__ hi,
                                              bf16* __restrict__ lo,
                                              int K, int N)
{
    __shared__ float t[64][65];
    const int n0 = blockIdx.x * 64, k0 = blockIdx.y * 64;
    const int tid = threadIdx.x;
    #pragma unroll
    for (int i = 0; i < 4; i++) {
        int idx = tid + i * 256;
        int r = idx >> 4, c4 = (idx & 15) << 2;
        float4 v = *(const float4*)&W[(size_t)(k0 + r) * N + n0 + c4];
        t[r][c4 + 0] = v.x; t[r][c4 + 1] = v.y;
        t[r][c4 + 2] = v.z; t[r][c4 + 3] = v.w;
    }
    __syncthreads();
    const int kc = tid & 7;
    #pragma unroll
    for (int p = 0; p < 2; p++) {
        int nl = (tid >> 3) + p * 32;
        int n = n0 + nl;
        bf16 h8[8], l8[8];
        #pragma unroll
        for (int j = 0; j < 8; j++) {
            float v = t[kc * 8 + j][nl];
            h8[j] = __float2bfloat16(v);
            l8[j] = __float2bfloat16(v - __bfloat162float(h8[j]));
        }
        *(uint4*)&hi[(size_t)n * K + k0 + kc * 8] = *(uint4*)h8;
        *(uint4*)&lo[(size_t)n * K + k0 + kc * 8] = *(uint4*)l8;
    }
}

__global__ void pack_bqkv(const float* __restrict__ bq, const float* __restrict__ bk,
                          const float* __restrict__ bv, float* __restrict__ out)
{
    int i = blockIdx.x * 256 + threadIdx.x;
    if (i >= LL * 3 * CC) return;
    int l = i / (3 * CC), c = i % (3 * CC);
    float v = (c < CC) ? bq[l * CC + c]
            : (c < 2 * CC) ? bk[l * CC + c - CC] : bv[l * CC + c - 2 * CC];
    out[i] = v;
}

// ---------------------------------------------------------------------------
// Embedding
// ---------------------------------------------------------------------------
__global__ void embed_kernel(const int* __restrict__ idx,
                             const float* __restrict__ tok,
                             const float* __restrict__ pos,
                             float* __restrict__ x)
{
    int i  = blockIdx.x * blockDim.x + threadIdx.x;
    int c4 = (i & 127) << 2;
    int bt = i >> 7;
    int t  = bt & (TT - 1);
    int row = idx[bt];
    float4 a = *(const float4*)&tok[row * CC + c4];
    float4 p = *(const float4*)&pos[t   * CC + c4];
    float4 o;
    o.x = a.x + p.x; o.y = a.y + p.y; o.z = a.z + p.z; o.w = a.w + p.w;
    *(float4*)&x[bt * CC + c4] = o;
}

// ---------------------------------------------------------------------------
// LayerNorm -> split bf16 hi/lo outputs
// ---------------------------------------------------------------------------
__global__ __launch_bounds__(128) void ln_split(const float* __restrict__ x,
                                                const float* __restrict__ w,
                                                const float* __restrict__ b,
                                                bf16* __restrict__ ohi,
                                                bf16* __restrict__ olo)
{
    __shared__ float red[4];
    const int row = blockIdx.x;
    const int tid = threadIdx.x;

    float4 v = *(const float4*)&x[row * CC + tid * 4];
    float s = v.x + v.y + v.z + v.w;
    #pragma unroll
    for (int o = 16; o; o >>= 1) s += __shfl_xor_sync(0xffffffffu, s, o);
    if ((tid & 31) == 0) red[tid >> 5] = s;
    __syncthreads();
    float mean = (red[0] + red[1] + red[2] + red[3]) * (1.0f / CC);

    float d0 = v.x - mean, d1 = v.y - mean, d2 = v.z - mean, d3 = v.w - mean;
    float ss = d0*d0 + d1*d1 + d2*d2 + d3*d3;
    #pragma unroll
    for (int o = 16; o; o >>= 1) ss += __shfl_xor_sync(0xffffffffu, ss, o);
    __syncthreads();
    if ((tid & 31) == 0) red[tid >> 5] = ss;
    __syncthreads();
    float var  = (red[0] + red[1] + red[2] + red[3]) * (1.0f / CC);
    float rstd = rsqrtf(var + 1e-5f);

    float4 wv = *(const float4*)&w[tid * 4];
    float4 bv = *(const float4*)&b[tid * 4];
    float o4[4];
    o4[0] = d0 * rstd * wv.x + bv.x;
    o4[1] = d1 * rstd * wv.y + bv.y;
    o4[2] = d2 * rstd * wv.z + bv.z;
    o4[3] = d3 * rstd * wv.w + bv.w;

    bf16 hi[4], lo[4];
    #pragma unroll
    for (int j = 0; j < 4; j++) {
        hi[j] = __float2bfloat16(o4[j]);
        lo[j] = __float2bfloat16(o4[j] - __bfloat162float(hi[j]));
    }
    *(uint2*)&ohi[row * CC + tid * 4] = *(uint2*)hi;
    *(uint2*)&olo[row * CC + tid * 4] = *(uint2*)lo;
}

// ---------------------------------------------------------------------------
// Tensor-core GEMM, pre-split bf16 operands (hi*hi+hi*lo+lo*hi, fp32 accum).
// ---------------------------------------------------------------------------
#define SWZ(r) ((((r) >> 1) & 3) << 2)

__device__ __forceinline__ void mma_bf16(float* c, const uint32_t* a, const uint32_t* b)
{
    asm volatile(
        "mma.sync.aligned.m16n8k16.row.col.f32.bf16.bf16.f32 "
        "{%0,%1,%2,%3}, {%4,%5,%6,%7}, {%8,%9}, {%0,%1,%2,%3};"
        : "+f"(c[0]), "+f"(c[1]), "+f"(c[2]), "+f"(c[3])
        : "r"(a[0]), "r"(a[1]), "r"(a[2]), "r"(a[3]), "r"(b[0]), "r"(b[1]));
}

__device__ __forceinline__ void cp16(uint32_t dst, const void* src)
{
    asm volatile("cp.async.cg.shared.global [%0], [%1], 16;\n"
                 :: "r"(dst), "l"(src));
}

template<int MODE, int WM>
__global__ __launch_bounds__(WM * 64) void gemm_tc2(
    const bf16* __restrict__ Ah, const bf16* __restrict__ Al,
    const bf16* __restrict__ Bh, const bf16* __restrict__ Bl,
    const float* __restrict__ bias, const float* __restrict__ resid,
    float* __restrict__ C, bf16* __restrict__ Chi, bf16* __restrict__ Clo,
    int M, int N, int K)
{
    constexpr int BM  = WM * 32;
    constexpr int NT  = WM * 64;
    constexpr int LA  = (WM == 4) ? 9 : 8;    // log2(BM*4) A-chunks per hl
    constexpr int BPT = 512 / NT;             // B chunks per thread

    __shared__ __align__(16) uint32_t As[2][2][BM][16];
    __shared__ __align__(16) uint32_t Bs[2][2][64][16];

    const int tid = threadIdx.x;
    const int lid = tid & 31;
    const int wid = tid >> 5;
    const int warp_m = wid % WM;
    const int warp_n = wid / WM;
    const int bm = blockIdx.y * BM;
    const int bn = blockIdx.x * 64;

    float acc[2][4][4];
    #pragma unroll
    for (int i = 0; i < 2; i++)
        #pragma unroll
        for (int j = 0; j < 4; j++)
            #pragma unroll
            for (int q = 0; q < 4; q++) acc[i][j][q] = 0.0f;

    auto load_stage = [&](int st, int k0) {
        #pragma unroll
        for (int i = 0; i < 4; i++) {
            int id  = tid + i * NT;
            int c   = id & 3;
            int row = (id >> 2) & (BM - 1);
            int hl  = id >> LA;
            const bf16* src = (hl ? Al : Ah) + (size_t)(bm + row) * K + k0 + c * 8;
            uint32_t dst = (uint32_t)__cvta_generic_to_shared(
                &As[st][hl][row][(c ^ ((row >> 1) & 3)) << 2]);
            cp16(dst, src);
        }
        #pragma unroll
        for (int i = 0; i < BPT; i++) {
            int id = tid + i * NT;
            int c  = id & 3;
            int n  = (id >> 2) & 63;
            int hl = id >> 8;
            const bf16* src = (hl ? Bl : Bh) + (size_t)(bn + n) * K + k0 + c * 8;
            uint32_t dst = (uint32_t)__cvta_generic_to_shared(
                &Bs[st][hl][n][(c ^ ((n >> 1) & 3)) << 2]);
            cp16(dst, src);
        }
    };

    const int nst = K / 32;
    load_stage(0, 0);
    asm volatile("cp.async.commit_group;" ::: "memory");
    load_stage(1, 32);
    asm volatile("cp.async.commit_group;" ::: "memory");

    int buf = 0;
    for (int st = 0; st < nst; st++) {
        if (st == nst - 1) asm volatile("cp.async.wait_group 0;" ::: "memory");
        else               asm volatile("cp.async.wait_group 1;" ::: "memory");
        __syncthreads();

        #pragma unroll
        for (int s = 0; s <= 8; s += 8) {
            const int c = lid & 3;
            uint32_t Af[2][2][4];
            uint32_t Bf[2][4][2];
            #pragma unroll
            for (int mt = 0; mt < 2; mt++) {
                int m0 = warp_m * 32 + mt * 16 + (lid >> 2);
                int m1 = m0 + 8;
                int p0 = (s + c)     ^ SWZ(m0);
                int p1 = (s + c)     ^ SWZ(m1);
                int p2 = (s + 4 + c) ^ SWZ(m0);
                int p3 = (s + 4 + c) ^ SWZ(m1);
                #pragma unroll
                for (int hl = 0; hl < 2; hl++) {
                    Af[hl][mt][0] = As[buf][hl][m0][p0];
                    Af[hl][mt][1] = As[buf][hl][m1][p1];
                    Af[hl][mt][2] = As[buf][hl][m0][p2];
                    Af[hl][mt][3] = As[buf][hl][m1][p3];
                }
            }
            #pragma unroll
            for (int nt = 0; nt < 4; nt++) {
                int n0 = warp_n * 32 + nt * 8 + (lid >> 2);
                int p0 = (s + c)     ^ SWZ(n0);
                int p1 = (s + 4 + c) ^ SWZ(n0);
                #pragma unroll
                for (int hl = 0; hl < 2; hl++) {
                    Bf[hl][nt][0] = Bs[buf][hl][n0][p0];
                    Bf[hl][nt][1] = Bs[buf][hl][n0][p1];
                }
            }
            #pragma unroll
            for (int mt = 0; mt < 2; mt++)
                #pragma unroll
                for (int nt = 0; nt < 4; nt++) {
                    mma_bf16(acc[mt][nt], Af[0][mt], Bf[0][nt]);   // hi*hi
                    mma_bf16(acc[mt][nt], Af[0][mt], Bf[1][nt]);   // hi*lo
                    mma_bf16(acc[mt][nt], Af[1][mt], Bf[0][nt]);   // lo*hi
                }
        }

        if (st + 2 < nst) {
            __syncthreads();
            load_stage(buf, (st + 2) * 32);
            asm volatile("cp.async.commit_group;" ::: "memory");
        }
        buf ^= 1;
    }

    #pragma unroll
    for (int mt = 0; mt < 2; mt++) {
        #pragma unroll
        for (int nt = 0; nt < 4; nt++) {
            int r0 = bm + warp_m * 32 + mt * 16 + (lid >> 2);
            int cc = bn + warp_n * 32 + nt * 8 + ((lid & 3) << 1);
            float2 bb = make_float2(0.0f, 0.0f);
            if (bias) bb = *(const float2*)(bias + cc);
            float* a4 = acc[mt][nt];
            #pragma unroll
            for (int half = 0; half < 2; half++) {
                int row = r0 + half * 8;
                float o0 = a4[half * 2 + 0] + bb.x;
                float o1 = a4[half * 2 + 1] + bb.y;
                if (MODE == 1) {
                    float2 rr = *(const float2*)(resid + (size_t)row * N + cc);
                    o0 += rr.x; o1 += rr.y;
                }
                if (MODE == 2) {
                    o0 = 0.5f * o0 * (1.0f + erff(o0 * 0.70710678118654752f));
                    o1 = 0.5f * o1 * (1.0f + erff(o1 * 0.70710678118654752f));
                    __nv_bfloat162 h2, l2;
                    h2.x = __float2bfloat16(o0);
                    h2.y = __float2bfloat16(o1);
                    l2.x = __float2bfloat16(o0 - __bfloat162float(h2.x));
                    l2.y = __float2bfloat16(o1 - __bfloat162float(h2.y));
                    *(__nv_bfloat162*)(Chi + (size_t)row * N + cc) = h2;
                    *(__nv_bfloat162*)(Clo + (size_t)row * N + cc) = l2;
                } else {
                    *(float2*)(C + (size_t)row * N + cc) = make_float2(o0, o1);
                }
            }
        }
    }
}

// ---------------------------------------------------------------------------
// Flash attention (fp32, causal), vectorized LDS.128 with XOR swizzles.
// 32 q-rows per block, 256 threads (8 per row). Reads fused qkv [M][1536].
// d-slice per thread: [sb*4, sb*4+4) U [32+sb*4, 32+sb*4+4).
// ---------------------------------------------------------------------------
__global__ __launch_bounds__(256) void attn_kernel(
    const float* __restrict__ QKV, bf16* __restrict__ Yh, bf16* __restrict__ Yl)
{
    const int qt = blockIdx.x;   // 32-row query tile
    const int h  = blockIdx.y;
    const int b  = blockIdx.z;

    __shared__ float Qs[32][64];   // chunks: [r][d4 ^ (r&7)]
    __shared__ float Ks[64][64];   // chunks: [key][d4 ^ ((key>>2)&7)]
    __shared__ float Vs[64][64];   // same swizzle as Ks
    __shared__ float Ps[32][64];   // scalar: [r][s ^ ((r&3)<<3)]

    const int tid = threadIdx.x;
    const int sb  = tid & 7;
    const int r   = tid >> 3;      // 0..31
    const int qg  = qt * 32 + r;
    const int ST  = 3 * CC;

    // load Q tile (32 rows x 16 chunks)
    for (int i = tid; i < 512; i += 256) {
        int rr = i >> 4, c4 = i & 15;
        ((float4*)Qs)[rr * 16 + (c4 ^ (rr & 7))] =
            *(const float4*)&QKV[(size_t)(b * TT + qt * 32 + rr) * ST + h * DD + c4 * 4];
    }

    float m = -1e30f, l = 0.0f;
    float4 acc0 = make_float4(0.f, 0.f, 0.f, 0.f);
    float4 acc1 = make_float4(0.f, 0.f, 0.f, 0.f);
    const int nkt = (qt >> 1) + 1;

    for (int kt = 0; kt < nkt; kt++) {
        __syncthreads();
        for (int i = tid; i < 1024; i += 256) {
            int rr = i >> 4, c4 = i & 15;
            size_t g = (size_t)(b * TT + kt * 64 + rr) * ST + h * DD + c4 * 4;
            int sw = rr * 16 + (c4 ^ ((rr >> 2) & 7));
            ((float4*)Ks)[sw] = *(const float4*)&QKV[g + CC];
            ((float4*)Vs)[sw] = *(const float4*)&QKV[g + 2 * CC];
        }
        __syncthreads();

        // scores: 8 keys per thread = {sb*4+jj} U {32+sb*4+jj}
        float sv[8];
        #pragma unroll
        for (int e = 0; e < 8; e++) sv[e] = 0.0f;
        #pragma unroll 4
        for (int d4 = 0; d4 < 16; d4++) {
            float4 qv = ((float4*)Qs)[r * 16 + (d4 ^ (r & 7))];
            #pragma unroll
            for (int half = 0; half < 2; half++)
                #pragma unroll
                for (int jj = 0; jj < 4; jj++) {
                    int key = half * 32 + sb * 4 + jj;
                    float4 kv = ((float4*)Ks)[key * 16 + (d4 ^ sb)];
                    sv[half * 4 + jj] += qv.x * kv.x + qv.y * kv.y
                                       + qv.z * kv.z + qv.w * kv.w;
                }
        }

        float tmax = -1e30f;
        #pragma unroll
        for (int e = 0; e < 8; e++) {
            int key = (e >> 2) * 32 + sb * 4 + (e & 3);
            int kgl = kt * 64 + key;
            sv[e] = (kgl <= qg) ? sv[e] * 0.125f : -1e30f;
            tmax = fmaxf(tmax, sv[e]);
        }
        #pragma unroll
        for (int o = 4; o; o >>= 1)
            tmax = fmaxf(tmax, __shfl_xor_sync(0xffffffffu, tmax, o, 8));

        float m_new = fmaxf(m, tmax);
        float psum = 0.0f;
        #pragma unroll
        for (int e = 0; e < 8; e++) {
            int key = (e >> 2) * 32 + sb * 4 + (e & 3);
            float p = __expf(sv[e] - m_new);
            Ps[r][key ^ ((r & 3) << 3)] = p;
            psum += p;
        }
        #pragma unroll
        for (int o = 4; o; o >>= 1)
            psum += __shfl_xor_sync(0xffffffffu, psum, o, 8);

        float alpha = __expf(m - m_new);
        m = m_new;
        l = l * alpha + psum;
        acc0.x *= alpha; acc0.y *= alpha; acc0.z *= alpha; acc0.w *= alpha;
        acc1.x *= alpha; acc1.y *= alpha; acc1.z *= alpha; acc1.w *= alpha;
        __syncwarp();

        #pragma unroll 4
        for (int s = 0; s < 64; s++) {
            float p = Ps[r][s ^ ((r & 3) << 3)];
            int swz = (s >> 2) & 7;
            float4 v0 = ((float4*)Vs)[s * 16 + (sb ^ swz)];
            float4 v1 = ((float4*)Vs)[s * 16 + ((sb + 8) ^ swz)];
            acc0.x += p * v0.x; acc0.y += p * v0.y;
            acc0.z += p * v0.z; acc0.w += p * v0.w;
            acc1.x += p * v1.x; acc1.y += p * v1.y;
            acc1.z += p * v1.z; acc1.w += p * v1.w;
        }
        __syncwarp();
    }

    const float inv_l = 1.0f / l;
    const size_t o = (size_t)(b * TT + qg) * CC + h * DD;
    float vv[8] = {acc0.x * inv_l, acc0.y * inv_l, acc0.z * inv_l, acc0.w * inv_l,
                   acc1.x * inv_l, acc1.y * inv_l, acc1.z * inv_l, acc1.w * inv_l};
    bf16 hh[8], ll[8];
    #pragma unroll
    for (int j = 0; j < 8; j++) {
        hh[j] = __float2bfloat16(vv[j]);
        ll[j] = __float2bfloat16(vv[j] - __bfloat162float(hh[j]));
    }
    *(uint2*)&Yh[o + sb * 4]      = *(uint2*)&hh[0];
    *(uint2*)&Yh[o + 32 + sb * 4] = *(uint2*)&hh[4];
    *(uint2*)&Yl[o + sb * 4]      = *(uint2*)&ll[0];
    *(uint2*)&Yl[o + 32 + sb * 4] = *(uint2*)&ll[4];
}

// ---------------------------------------------------------------------------
// Launch
// ---------------------------------------------------------------------------
extern "C" void kernel_launch(void* const* d_in, const int* in_sizes, int n_in,
                              void* d_out, int out_size)
{
    const int*   idx   = (const int*)  d_in[0];
    const float* tok   = (const float*)d_in[1];
    const float* pos   = (const float*)d_in[2];
    const float* ln1w  = (const float*)d_in[3];
    const float* ln1b  = (const float*)d_in[4];
    const float* Wq    = (const float*)d_in[5];
    const float* bq    = (const float*)d_in[6];
    const float* Wk    = (const float*)d_in[7];
    const float* bk    = (const float*)d_in[8];
    const float* Wv    = (const float*)d_in[9];
    const float* bv    = (const float*)d_in[10];
    const float* Wo    = (const float*)d_in[11];
    const float* bo    = (const float*)d_in[12];
    const float* ln2w  = (const float*)d_in[13];
    const float* ln2b  = (const float*)d_in[14];
    const float* W1    = (const float*)d_in[15];
    const float* b1    = (const float*)d_in[16];
    const float* W2    = (const float*)d_in[17];
    const float* b2    = (const float*)d_in[18];
    const float* lnfw  = (const float*)d_in[19];
    const float* lnfb  = (const float*)d_in[20];
    const float* Whead = (const float*)d_in[21];
    float* out = (float*)d_out;

    float *x, *qkv, *bqkv;
    bf16 *h_hi, *h_lo, *y_hi, *y_lo, *h1_hi, *h1_lo;
    bf16 *wqkv_hi, *wqkv_lo, *wo_hi, *wo_lo, *w1_hi, *w1_lo, *w2_hi, *w2_lo, *wh_hi, *wh_lo;
    cudaGetSymbolAddress((void**)&x,     g_x);
    cudaGetSymbolAddress((void**)&qkv,   g_qkv);
    cudaGetSymbolAddress((void**)&bqkv,  g_bqkv);
    cudaGetSymbolAddress((void**)&h_hi,  g_h_hi);
    cudaGetSymbolAddress((void**)&h_lo,  g_h_lo);
    cudaGetSymbolAddress((void**)&y_hi,  g_y_hi);
    cudaGetSymbolAddress((void**)&y_lo,  g_y_lo);
    cudaGetSymbolAddress((void**)&h1_hi, g_h1_hi);
    cudaGetSymbolAddress((void**)&h1_lo, g_h1_lo);
    cudaGetSymbolAddress((void**)&wqkv_hi, g_wqkv_hi);
    cudaGetSymbolAddress((void**)&wqkv_lo, g_wqkv_lo);
    cudaGetSymbolAddress((void**)&wo_hi,   g_wo_hi);
    cudaGetSymbolAddress((void**)&wo_lo,   g_wo_lo);
    cudaGetSymbolAddress((void**)&w1_hi,   g_w1_hi);
    cudaGetSymbolAddress((void**)&w1_lo,   g_w1_lo);
    cudaGetSymbolAddress((void**)&w2_hi,   g_w2_hi);
    cudaGetSymbolAddress((void**)&w2_lo,   g_w2_lo);
    cudaGetSymbolAddress((void**)&wh_hi,   g_wh_hi);
    cudaGetSymbolAddress((void**)&wh_lo,   g_wh_lo);

    const int M = BB * TT;

    // ---- prepack weights (transpose + bf16 split), 64x64 tiles ----
    for (int l = 0; l < LL; l++) {
        const size_t w  = (size_t)l * CC * CC;
        const size_t w1 = (size_t)l * 4 * CC * CC;
        pack_w<<<dim3(8, 8), 256>>>(Wq + w, wqkv_hi + (size_t)l*3*CC*CC,
                                    wqkv_lo + (size_t)l*3*CC*CC, CC, CC);
        pack_w<<<dim3(8, 8), 256>>>(Wk + w, wqkv_hi + (size_t)l*3*CC*CC + CC*CC,
                                    wqkv_lo + (size_t)l*3*CC*CC + CC*CC, CC, CC);
        pack_w<<<dim3(8, 8), 256>>>(Wv + w, wqkv_hi + (size_t)l*3*CC*CC + 2*CC*CC,
                                    wqkv_lo + (size_t)l*3*CC*CC + 2*CC*CC, CC, CC);
        pack_w<<<dim3(8, 8), 256>>>(Wo + w, wo_hi + w, wo_lo + w, CC, CC);
        pack_w<<<dim3(32, 8), 256>>>(W1 + w1, w1_hi + w1, w1_lo + w1, CC, 4 * CC);
        pack_w<<<dim3(8, 32), 256>>>(W2 + w1, w2_hi + w1, w2_lo + w1, 4 * CC, CC);
    }
    pack_w<<<dim3(VV / 64, 8), 256>>>(Whead, wh_hi, wh_lo, CC, VV);
    pack_bqkv<<<(LL * 3 * CC + 255) / 256, 256>>>(bq, bk, bv, bqkv);

    embed_kernel<<<(M * CC / 4 + 255) / 256, 256>>>(idx, tok, pos, x);

    for (int l = 0; l < LL; l++) {
        const size_t bOff  = (size_t)l * CC;
        const size_t b1Off = (size_t)l * 4 * CC;

        ln_split<<<M, 128>>>(x, ln1w + bOff, ln1b + bOff, h_hi, h_lo);

        gemm_tc2<0, 4><<<dim3(24, 16), 256>>>(
            h_hi, h_lo, wqkv_hi + (size_t)l*3*CC*CC, wqkv_lo + (size_t)l*3*CC*CC,
            bqkv + (size_t)l*3*CC, nullptr, qkv, nullptr, nullptr, M, 3 * CC, CC);

        attn_kernel<<<dim3(TT / 32, HH, BB), 256>>>(qkv, y_hi, y_lo);

        gemm_tc2<1, 2><<<dim3(8, 32), 128>>>(
            y_hi, y_lo, wo_hi + (size_t)l*CC*CC, wo_lo + (size_t)l*CC*CC,
            bo + bOff, x, x, nullptr, nullptr, M, CC, CC);

        ln_split<<<M, 128>>>(x, ln2w + bOff, ln2b + bOff, h_hi, h_lo);

        gemm_tc2<2, 4><<<dim3(32, 16), 256>>>(
            h_hi, h_lo, w1_hi + (size_t)l*4*CC*CC, w1_lo + (size_t)l*4*CC*CC,
            b1 + b1Off, nullptr, nullptr, h1_hi, h1_lo, M, 4 * CC, CC);

        gemm_tc2<1, 2><<<dim3(8, 32), 128>>>(
            h1_hi, h1_lo, w2_hi + (size_t)l*4*CC*CC, w2_lo + (size_t)l*4*CC*CC,
            b2 + bOff, x, x, nullptr, nullptr, M, CC, 4 * CC);
    }

    ln_split<<<M, 128>>>(x, lnfw, lnfb, h_hi, h_lo);
    gemm_tc2<0, 4><<<dim3(VV / 64, 16), 256>>>(
        h_hi, h_lo, wh_hi, wh_lo, nullptr, nullptr, out, nullptr, nullptr, M, VV, CC);
}

// round 12
// speedup vs baseline: 1.0296x; 1.0296x over previous
#include <cuda_runtime.h>
#include <cuda_bf16.h>
#include <math.h>
#include <stdint.h>

#define BB 2
#define TT 1024
#define CC 512
#define HH 8
#define DD 64
#define LL 4
#define VV 32000

typedef __nv_bfloat16 bf16;

// ---------------- scratch (no cudaMalloc allowed) ----------------
__device__ float g_x   [BB*TT*CC];          // residual stream (fp32)
__device__ float g_qkv [BB*TT*3*CC];        // fused qkv (fp32)
__device__ bf16  g_h_hi[BB*TT*CC],  g_h_lo[BB*TT*CC];     // LN out split
__device__ bf16  g_y_hi[BB*TT*CC],  g_y_lo[BB*TT*CC];     // attn out split
__device__ bf16  g_h1_hi[BB*TT*4*CC], g_h1_lo[BB*TT*4*CC];// MLP hidden split
// packed weights (transposed to [N][K], split hi/lo)
__device__ bf16 g_wqkv_hi[LL*3*CC*CC], g_wqkv_lo[LL*3*CC*CC];
__device__ bf16 g_wo_hi  [LL*CC*CC],   g_wo_lo  [LL*CC*CC];
__device__ bf16 g_w1_hi  [LL*4*CC*CC], g_w1_lo  [LL*4*CC*CC];
__device__ bf16 g_w2_hi  [LL*4*CC*CC], g_w2_lo  [LL*4*CC*CC];
__device__ bf16 g_wh_hi  [VV*CC],      g_wh_lo  [VV*CC];
__device__ float g_bqkv [LL*3*CC];

// ---------------------------------------------------------------------------
// Unified weight pack: ALL weights in one launch. Each block packs one 64x64
// tile: out_hi/lo[n][k] = split(W[k][n]). Block-id -> segment decode.
// Segments per layer (768 tiles): Wq(64) Wk(64) Wv(64) Wo(64) W1(256) W2(256).
// Then Whead (4000 tiles). Total 4*768 + 4000 = 7072 blocks.
// ---------------------------------------------------------------------------
__global__ __launch_bounds__(256) void pack_all(
    const float* __restrict__ Wq, const float* __restrict__ Wk,
    const float* __restrict__ Wv, const float* __restrict__ Wo,
    const float* __restrict__ W1, const float* __restrict__ W2,
    const float* __restrict__ Wh,
    bf16* __restrict__ wqkv_hi, bf16* __restrict__ wqkv_lo,
    bf16* __restrict__ wo_hi,   bf16* __restrict__ wo_lo,
    bf16* __restrict__ w1_hi,   bf16* __restrict__ w1_lo,
    bf16* __restrict__ w2_hi,   bf16* __restrict__ w2_lo,
    bf16* __restrict__ wh_hi,   bf16* __restrict__ wh_lo)
{
    const int bid = blockIdx.x;
    const float* W; bf16 *hi, *lo; int K, N, t;

    if (bid < 4 * 768) {
        const int l = bid / 768;
        const int r = bid % 768;
        const size_t w  = (size_t)l * CC * CC;
        const size_t w1 = (size_t)l * 4 * CC * CC;
        if (r < 192) {              // Wq / Wk / Wv -> fused qkv buffer
            const int which = r / 64;
            t = r % 64;
            W  = (which == 0 ? Wq : which == 1 ? Wk : Wv) + w;
            hi = wqkv_hi + (size_t)l * 3 * CC * CC + (size_t)which * CC * CC;
            lo = wqkv_lo + (size_t)l * 3 * CC * CC + (size_t)which * CC * CC;
            K = CC; N = CC;
        } else if (r < 256) {       // Wo
            t = r - 192;
            W = Wo + w; hi = wo_hi + w; lo = wo_lo + w;
            K = CC; N = CC;
        } else if (r < 512) {       // W1: K=512, N=2048
            t = r - 256;
            W = W1 + w1; hi = w1_hi + w1; lo = w1_lo + w1;
            K = CC; N = 4 * CC;
        } else {                    // W2: K=2048, N=512
            t = r - 512;
            W = W2 + w1; hi = w2_hi + w1; lo = w2_lo + w1;
            K = 4 * CC; N = CC;
        }
    } else {                        // Whead: K=512, N=32000
        t = bid - 4 * 768;
        W = Wh; hi = wh_hi; lo = wh_lo;
        K = CC; N = VV;
    }

    const int tiles_n = N >> 6;
    const int n0 = (t % tiles_n) << 6;
    const int k0 = (t / tiles_n) << 6;

    __shared__ float tl[64][65];
    const int tid = threadIdx.x;
    #pragma unroll
    for (int i = 0; i < 4; i++) {
        int idx = tid + i * 256;
        int r = idx >> 4, c4 = (idx & 15) << 2;
        float4 v = *(const float4*)&W[(size_t)(k0 + r) * N + n0 + c4];
        tl[r][c4 + 0] = v.x; tl[r][c4 + 1] = v.y;
        tl[r][c4 + 2] = v.z; tl[r][c4 + 3] = v.w;
    }
    __syncthreads();
    const int kc = tid & 7;
    #pragma unroll
    for (int p = 0; p < 2; p++) {
        int nl = (tid >> 3) + p * 32;
        int n = n0 + nl;
        bf16 h8[8], l8[8];
        #pragma unroll
        for (int j = 0; j < 8; j++) {
            float v = tl[kc * 8 + j][nl];
            h8[j] = __float2bfloat16(v);
            l8[j] = __float2bfloat16(v - __bfloat162float(h8[j]));
        }
        *(uint4*)&hi[(size_t)n * K + k0 + kc * 8] = *(uint4*)h8;
        *(uint4*)&lo[(size_t)n * K + k0 + kc * 8] = *(uint4*)l8;
    }
}

__global__ void pack_bqkv(const float* __restrict__ bq, const float* __restrict__ bk,
                          const float* __restrict__ bv, float* __restrict__ out)
{
    int i = blockIdx.x * 256 + threadIdx.x;
    if (i >= LL * 3 * CC) return;
    int l = i / (3 * CC), c = i % (3 * CC);
    float v = (c < CC) ? bq[l * CC + c]
            : (c < 2 * CC) ? bk[l * CC + c - CC] : bv[l * CC + c - 2 * CC];
    out[i] = v;
}

// ---------------------------------------------------------------------------
// Embedding
// ---------------------------------------------------------------------------
__global__ void embed_kernel(const int* __restrict__ idx,
                             const float* __restrict__ tok,
                             const float* __restrict__ pos,
                             float* __restrict__ x)
{
    int i  = blockIdx.x * blockDim.x + threadIdx.x;
    int c4 = (i & 127) << 2;
    int bt = i >> 7;
    int t  = bt & (TT - 1);
    int row = idx[bt];
    float4 a = *(const float4*)&tok[row * CC + c4];
    float4 p = *(const float4*)&pos[t   * CC + c4];
    float4 o;
    o.x = a.x + p.x; o.y = a.y + p.y; o.z = a.z + p.z; o.w = a.w + p.w;
    *(float4*)&x[bt * CC + c4] = o;
}

// ---------------------------------------------------------------------------
// LayerNorm -> split bf16 hi/lo outputs
// ---------------------------------------------------------------------------
__global__ __launch_bounds__(128) void ln_split(const float* __restrict__ x,
                                                const float* __restrict__ w,
                                                const float* __restrict__ b,
                                                bf16* __restrict__ ohi,
                                                bf16* __restrict__ olo)
{
    __shared__ float red[4];
    const int row = blockIdx.x;
    const int tid = threadIdx.x;

    float4 v = *(const float4*)&x[row * CC + tid * 4];
    float s = v.x + v.y + v.z + v.w;
    #pragma unroll
    for (int o = 16; o; o >>= 1) s += __shfl_xor_sync(0xffffffffu, s, o);
    if ((tid & 31) == 0) red[tid >> 5] = s;
    __syncthreads();
    float mean = (red[0] + red[1] + red[2] + red[3]) * (1.0f / CC);

    float d0 = v.x - mean, d1 = v.y - mean, d2 = v.z - mean, d3 = v.w - mean;
    float ss = d0*d0 + d1*d1 + d2*d2 + d3*d3;
    #pragma unroll
    for (int o = 16; o; o >>= 1) ss += __shfl_xor_sync(0xffffffffu, ss, o);
    __syncthreads();
    if ((tid & 31) == 0) red[tid >> 5] = ss;
    __syncthreads();
    float var  = (red[0] + red[1] + red[2] + red[3]) * (1.0f / CC);
    float rstd = rsqrtf(var + 1e-5f);

    float4 wv = *(const float4*)&w[tid * 4];
    float4 bv = *(const float4*)&b[tid * 4];
    float o4[4];
    o4[0] = d0 * rstd * wv.x + bv.x;
    o4[1] = d1 * rstd * wv.y + bv.y;
    o4[2] = d2 * rstd * wv.z + bv.z;
    o4[3] = d3 * rstd * wv.w + bv.w;

    bf16 hi[4], lo[4];
    #pragma unroll
    for (int j = 0; j < 4; j++) {
        hi[j] = __float2bfloat16(o4[j]);
        lo[j] = __float2bfloat16(o4[j] - __bfloat162float(hi[j]));
    }
    *(uint2*)&ohi[row * CC + tid * 4] = *(uint2*)hi;
    *(uint2*)&olo[row * CC + tid * 4] = *(uint2*)lo;
}

// ---------------------------------------------------------------------------
// Tensor-core GEMM, pre-split bf16 operands (hi*hi+hi*lo+lo*hi, fp32 accum).
// 2+ CTAs/SM forced via launch_bounds for latency hiding.
// ---------------------------------------------------------------------------
#define SWZ(r) ((((r) >> 1) & 3) << 2)

__device__ __forceinline__ void mma_bf16(float* c, const uint32_t* a, const uint32_t* b)
{
    asm volatile(
        "mma.sync.aligned.m16n8k16.row.col.f32.bf16.bf16.f32 "
        "{%0,%1,%2,%3}, {%4,%5,%6,%7}, {%8,%9}, {%0,%1,%2,%3};"
        : "+f"(c[0]), "+f"(c[1]), "+f"(c[2]), "+f"(c[3])
        : "r"(a[0]), "r"(a[1]), "r"(a[2]), "r"(a[3]), "r"(b[0]), "r"(b[1]));
}

__device__ __forceinline__ void cp16(uint32_t dst, const void* src)
{
    asm volatile("cp.async.cg.shared.global [%0], [%1], 16;\n"
                 :: "r"(dst), "l"(src));
}

template<int MODE, int WM>
__global__ __launch_bounds__(WM * 64, (WM == 4) ? 2 : 4) void gemm_tc2(
    const bf16* __restrict__ Ah, const bf16* __restrict__ Al,
    const bf16* __restrict__ Bh, const bf16* __restrict__ Bl,
    const float* __restrict__ bias, const float* __restrict__ resid,
    float* __restrict__ C, bf16* __restrict__ Chi, bf16* __restrict__ Clo,
    int M, int N, int K)
{
    constexpr int BM  = WM * 32;
    constexpr int NT  = WM * 64;
    constexpr int LA  = (WM == 4) ? 9 : 8;    // log2(BM*4) A-chunks per hl
    constexpr int BPT = 512 / NT;             // B chunks per thread

    __shared__ __align__(16) uint32_t As[2][2][BM][16];
    __shared__ __align__(16) uint32_t Bs[2][2][64][16];

    const int tid = threadIdx.x;
    const int lid = tid & 31;
    const int wid = tid >> 5;
    const int warp_m = wid % WM;
    const int warp_n = wid / WM;
    const int bm = blockIdx.y * BM;
    const int bn = blockIdx.x * 64;

    float acc[2][4][4];
    #pragma unroll
    for (int i = 0; i < 2; i++)
        #pragma unroll
        for (int j = 0; j < 4; j++)
            #pragma unroll
            for (int q = 0; q < 4; q++) acc[i][j][q] = 0.0f;

    auto load_stage = [&](int st, int k0) {
        #pragma unroll
        for (int i = 0; i < 4; i++) {
            int id  = tid + i * NT;
            int c   = id & 3;
            int row = (id >> 2) & (BM - 1);
            int hl  = id >> LA;
            const bf16* src = (hl ? Al : Ah) + (size_t)(bm + row) * K + k0 + c * 8;
            uint32_t dst = (uint32_t)__cvta_generic_to_shared(
                &As[st][hl][row][(c ^ ((row >> 1) & 3)) << 2]);
            cp16(dst, src);
        }
        #pragma unroll
        for (int i = 0; i < BPT; i++) {
            int id = tid + i * NT;
            int c  = id & 3;
            int n  = (id >> 2) & 63;
            int hl = id >> 8;
            const bf16* src = (hl ? Bl : Bh) + (size_t)(bn + n) * K + k0 + c * 8;
            uint32_t dst = (uint32_t)__cvta_generic_to_shared(
                &Bs[st][hl][n][(c ^ ((n >> 1) & 3)) << 2]);
            cp16(dst, src);
        }
    };

    const int nst = K / 32;
    load_stage(0, 0);
    asm volatile("cp.async.commit_group;" ::: "memory");
    load_stage(1, 32);
    asm volatile("cp.async.commit_group;" ::: "memory");

    int buf = 0;
    for (int st = 0; st < nst; st++) {
        if (st == nst - 1) asm volatile("cp.async.wait_group 0;" ::: "memory");
        else               asm volatile("cp.async.wait_group 1;" ::: "memory");
        __syncthreads();

        #pragma unroll
        for (int s = 0; s <= 8; s += 8) {
            const int c = lid & 3;
            uint32_t Af[2][2][4];
            uint32_t Bf[2][4][2];
            #pragma unroll
            for (int mt = 0; mt < 2; mt++) {
                int m0 = warp_m * 32 + mt * 16 + (lid >> 2);
                int m1 = m0 + 8;
                int p0 = (s + c)     ^ SWZ(m0);
                int p1 = (s + c)     ^ SWZ(m1);
                int p2 = (s + 4 + c) ^ SWZ(m0);
                int p3 = (s + 4 + c) ^ SWZ(m1);
                #pragma unroll
                for (int hl = 0; hl < 2; hl++) {
                    Af[hl][mt][0] = As[buf][hl][m0][p0];
                    Af[hl][mt][1] = As[buf][hl][m1][p1];
                    Af[hl][mt][2] = As[buf][hl][m0][p2];
                    Af[hl][mt][3] = As[buf][hl][m1][p3];
                }
            }
            #pragma unroll
            for (int nt = 0; nt < 4; nt++) {
                int n0 = warp_n * 32 + nt * 8 + (lid >> 2);
                int p0 = (s + c)     ^ SWZ(n0);
                int p1 = (s + 4 + c) ^ SWZ(n0);
                #pragma unroll
                for (int hl = 0; hl < 2; hl++) {
                    Bf[hl][nt][0] = Bs[buf][hl][n0][p0];
                    Bf[hl][nt][1] = Bs[buf][hl][n0][p1];
                }
            }
            #pragma unroll
            for (int mt = 0; mt < 2; mt++)
                #pragma unroll
                for (int nt = 0; nt < 4; nt++) {
                    mma_bf16(acc[mt][nt], Af[0][mt], Bf[0][nt]);   // hi*hi
                    mma_bf16(acc[mt][nt], Af[0][mt], Bf[1][nt]);   // hi*lo
                    mma_bf16(acc[mt][nt], Af[1][mt], Bf[0][nt]);   // lo*hi
                }
        }

        if (st + 2 < nst) {
            __syncthreads();
            load_stage(buf, (st + 2) * 32);
            asm volatile("cp.async.commit_group;" ::: "memory");
        }
        buf ^= 1;
    }

    #pragma unroll
    for (int mt = 0; mt < 2; mt++) {
        #pragma unroll
        for (int nt = 0; nt < 4; nt++) {
            int r0 = bm + warp_m * 32 + mt * 16 + (lid >> 2);
            int cc = bn + warp_n * 32 + nt * 8 + ((lid & 3) << 1);
            float2 bb = make_float2(0.0f, 0.0f);
            if (bias) bb = *(const float2*)(bias + cc);
            float* a4 = acc[mt][nt];
            #pragma unroll
            for (int half = 0; half < 2; half++) {
                int row = r0 + half * 8;
                float o0 = a4[half * 2 + 0] + bb.x;
                float o1 = a4[half * 2 + 1] + bb.y;
                if (MODE == 1) {
                    float2 rr = *(const float2*)(resid + (size_t)row * N + cc);
                    o0 += rr.x; o1 += rr.y;
                }
                if (MODE == 2) {
                    o0 = 0.5f * o0 * (1.0f + erff(o0 * 0.70710678118654752f));
                    o1 = 0.5f * o1 * (1.0f + erff(o1 * 0.70710678118654752f));
                    __nv_bfloat162 h2, l2;
                    h2.x = __float2bfloat16(o0);
                    h2.y = __float2bfloat16(o1);
                    l2.x = __float2bfloat16(o0 - __bfloat162float(h2.x));
                    l2.y = __float2bfloat16(o1 - __bfloat162float(h2.y));
                    *(__nv_bfloat162*)(Chi + (size_t)row * N + cc) = h2;
                    *(__nv_bfloat162*)(Clo + (size_t)row * N + cc) = l2;
                } else {
                    *(float2*)(C + (size_t)row * N + cc) = make_float2(o0, o1);
                }
            }
        }
    }
}

// ---------------------------------------------------------------------------
// Flash attention (fp32, causal), vectorized LDS.128 with XOR swizzles.
// 32 q-rows per block, 256 threads (8 per row). Reads fused qkv [M][1536].
// ---------------------------------------------------------------------------
__global__ __launch_bounds__(256) void attn_kernel(
    const float* __restrict__ QKV, bf16* __restrict__ Yh, bf16* __restrict__ Yl)
{
    const int qt = blockIdx.x;   // 32-row query tile
    const int h  = blockIdx.y;
    const int b  = blockIdx.z;

    __shared__ float Qs[32][64];   // chunks: [r][d4 ^ (r&7)]
    __shared__ float Ks[64][64];   // chunks: [key][d4 ^ ((key>>2)&7)]
    __shared__ float Vs[64][64];   // same swizzle as Ks
    __shared__ float Ps[32][64];   // scalar: [r][s ^ ((r&3)<<3)]

    const int tid = threadIdx.x;
    const int sb  = tid & 7;
    const int r   = tid >> 3;      // 0..31
    const int qg  = qt * 32 + r;
    const int ST  = 3 * CC;

    for (int i = tid; i < 512; i += 256) {
        int rr = i >> 4, c4 = i & 15;
        ((float4*)Qs)[rr * 16 + (c4 ^ (rr & 7))] =
            *(const float4*)&QKV[(size_t)(b * TT + qt * 32 + rr) * ST + h * DD + c4 * 4];
    }

    float m = -1e30f, l = 0.0f;
    float4 acc0 = make_float4(0.f, 0.f, 0.f, 0.f);
    float4 acc1 = make_float4(0.f, 0.f, 0.f, 0.f);
    const int nkt = (qt >> 1) + 1;

    for (int kt = 0; kt < nkt; kt++) {
        __syncthreads();
        for (int i = tid; i < 1024; i += 256) {
            int rr = i >> 4, c4 = i & 15;
            size_t g = (size_t)(b * TT + kt * 64 + rr) * ST + h * DD + c4 * 4;
            int sw = rr * 16 + (c4 ^ ((rr >> 2) & 7));
            ((float4*)Ks)[sw] = *(const float4*)&QKV[g + CC];
            ((float4*)Vs)[sw] = *(const float4*)&QKV[g + 2 * CC];
        }
        __syncthreads();

        float sv[8];
        #pragma unroll
        for (int e = 0; e < 8; e++) sv[e] = 0.0f;
        #pragma unroll 4
        for (int d4 = 0; d4 < 16; d4++) {
            float4 qv = ((float4*)Qs)[r * 16 + (d4 ^ (r & 7))];
            #pragma unroll
            for (int half = 0; half < 2; half++)
                #pragma unroll
                for (int jj = 0; jj < 4; jj++) {
                    int key = half * 32 + sb * 4 + jj;
                    float4 kv = ((float4*)Ks)[key * 16 + (d4 ^ sb)];
                    sv[half * 4 + jj] += qv.x * kv.x + qv.y * kv.y
                                       + qv.z * kv.z + qv.w * kv.w;
                }
        }

        float tmax = -1e30f;
        #pragma unroll
        for (int e = 0; e < 8; e++) {
            int key = (e >> 2) * 32 + sb * 4 + (e & 3);
            int kgl = kt * 64 + key;
            sv[e] = (kgl <= qg) ? sv[e] * 0.125f : -1e30f;
            tmax = fmaxf(tmax, sv[e]);
        }
        #pragma unroll
        for (int o = 4; o; o >>= 1)
            tmax = fmaxf(tmax, __shfl_xor_sync(0xffffffffu, tmax, o, 8));

        float m_new = fmaxf(m, tmax);
        float psum = 0.0f;
        #pragma unroll
        for (int e = 0; e < 8; e++) {
            int key = (e >> 2) * 32 + sb * 4 + (e & 3);
            float p = __expf(sv[e] - m_new);
            Ps[r][key ^ ((r & 3) << 3)] = p;
            psum += p;
        }
        #pragma unroll
        for (int o = 4; o; o >>= 1)
            psum += __shfl_xor_sync(0xffffffffu, psum, o, 8);

        float alpha = __expf(m - m_new);
        m = m_new;
        l = l * alpha + psum;
        acc0.x *= alpha; acc0.y *= alpha; acc0.z *= alpha; acc0.w *= alpha;
        acc1.x *= alpha; acc1.y *= alpha; acc1.z *= alpha; acc1.w *= alpha;
        __syncwarp();

        #pragma unroll 4
        for (int s = 0; s < 64; s++) {
            float p = Ps[r][s ^ ((r & 3) << 3)];
            int swz = (s >> 2) & 7;
            float4 v0 = ((float4*)Vs)[s * 16 + (sb ^ swz)];
            float4 v1 = ((float4*)Vs)[s * 16 + ((sb + 8) ^ swz)];
            acc0.x += p * v0.x; acc0.y += p * v0.y;
            acc0.z += p * v0.z; acc0.w += p * v0.w;
            acc1.x += p * v1.x; acc1.y += p * v1.y;
            acc1.z += p * v1.z; acc1.w += p * v1.w;
        }
        __syncwarp();
    }

    const float inv_l = 1.0f / l;
    const size_t o = (size_t)(b * TT + qg) * CC + h * DD;
    float vv[8] = {acc0.x * inv_l, acc0.y * inv_l, acc0.z * inv_l, acc0.w * inv_l,
                   acc1.x * inv_l, acc1.y * inv_l, acc1.z * inv_l, acc1.w * inv_l};
    bf16 hh[8], ll[8];
    #pragma unroll
    for (int j = 0; j < 8; j++) {
        hh[j] = __float2bfloat16(vv[j]);
        ll[j] = __float2bfloat16(vv[j] - __bfloat162float(hh[j]));
    }
    *(uint2*)&Yh[o + sb * 4]      = *(uint2*)&hh[0];
    *(uint2*)&Yh[o + 32 + sb * 4] = *(uint2*)&hh[4];
    *(uint2*)&Yl[o + sb * 4]      = *(uint2*)&ll[0];
    *(uint2*)&Yl[o + 32 + sb * 4] = *(uint2*)&ll[4];
}

// ---------------------------------------------------------------------------
// Launch
// ---------------------------------------------------------------------------
extern "C" void kernel_launch(void* const* d_in, const int* in_sizes, int n_in,
                              void* d_out, int out_size)
{
    const int*   idx   = (const int*)  d_in[0];
    const float* tok   = (const float*)d_in[1];
    const float* pos   = (const float*)d_in[2];
    const float* ln1w  = (const float*)d_in[3];
    const float* ln1b  = (const float*)d_in[4];
    const float* Wq    = (const float*)d_in[5];
    const float* bq    = (const float*)d_in[6];
    const float* Wk    = (const float*)d_in[7];
    const float* bk    = (const float*)d_in[8];
    const float* Wv    = (const float*)d_in[9];
    const float* bv    = (const float*)d_in[10];
    const float* Wo    = (const float*)d_in[11];
    const float* bo    = (const float*)d_in[12];
    const float* ln2w  = (const float*)d_in[13];
    const float* ln2b  = (const float*)d_in[14];
    const float* W1    = (const float*)d_in[15];
    const float* b1    = (const float*)d_in[16];
    const float* W2    = (const float*)d_in[17];
    const float* b2    = (const float*)d_in[18];
    const float* lnfw  = (const float*)d_in[19];
    const float* lnfb  = (const float*)d_in[20];
    const float* Whead = (const float*)d_in[21];
    float* out = (float*)d_out;

    float *x, *qkv, *bqkv;
    bf16 *h_hi, *h_lo, *y_hi, *y_lo, *h1_hi, *h1_lo;
    bf16 *wqkv_hi, *wqkv_lo, *wo_hi, *wo_lo, *w1_hi, *w1_lo, *w2_hi, *w2_lo, *wh_hi, *wh_lo;
    cudaGetSymbolAddress((void**)&x,     g_x);
    cudaGetSymbolAddress((void**)&qkv,   g_qkv);
    cudaGetSymbolAddress((void**)&bqkv,  g_bqkv);
    cudaGetSymbolAddress((void**)&h_hi,  g_h_hi);
    cudaGetSymbolAddress((void**)&h_lo,  g_h_lo);
    cudaGetSymbolAddress((void**)&y_hi,  g_y_hi);
    cudaGetSymbolAddress((void**)&y_lo,  g_y_lo);
    cudaGetSymbolAddress((void**)&h1_hi, g_h1_hi);
    cudaGetSymbolAddress((void**)&h1_lo, g_h1_lo);
    cudaGetSymbolAddress((void**)&wqkv_hi, g_wqkv_hi);
    cudaGetSymbolAddress((void**)&wqkv_lo, g_wqkv_lo);
    cudaGetSymbolAddress((void**)&wo_hi,   g_wo_hi);
    cudaGetSymbolAddress((void**)&wo_lo,   g_wo_lo);
    cudaGetSymbolAddress((void**)&w1_hi,   g_w1_hi);
    cudaGetSymbolAddress((void**)&w1_lo,   g_w1_lo);
    cudaGetSymbolAddress((void**)&w2_hi,   g_w2_hi);
    cudaGetSymbolAddress((void**)&w2_lo,   g_w2_lo);
    cudaGetSymbolAddress((void**)&wh_hi,   g_wh_hi);
    cudaGetSymbolAddress((void**)&wh_lo,   g_wh_lo);

    const int M = BB * TT;

    // 1: single pack launch for ALL weights (7072 tiles)
    pack_all<<<4 * 768 + (VV / 64) * (CC / 64), 256>>>(
        Wq, Wk, Wv, Wo, W1, W2, Whead,
        wqkv_hi, wqkv_lo, wo_hi, wo_lo, w1_hi, w1_lo, w2_hi, w2_lo, wh_hi, wh_lo);
    // 2
    pack_bqkv<<<(LL * 3 * CC + 255) / 256, 256>>>(bq, bk, bv, bqkv);
    // 3
    embed_kernel<<<(M * CC / 4 + 255) / 256, 256>>>(idx, tok, pos, x);

    for (int l = 0; l < LL; l++) {
        const size_t bOff  = (size_t)l * CC;
        const size_t b1Off = (size_t)l * 4 * CC;

        // 4 (first layer) ...
        ln_split<<<M, 128>>>(x, ln1w + bOff, ln1b + bOff, h_hi, h_lo);
        // 5
        gemm_tc2<0, 4><<<dim3(24, 16), 256>>>(
            h_hi, h_lo, wqkv_hi + (size_t)l*3*CC*CC, wqkv_lo + (size_t)l*3*CC*CC,
            bqkv + (size_t)l*3*CC, nullptr, qkv, nullptr, nullptr, M, 3 * CC, CC);
        // 6  <- ncu sample target
        attn_kernel<<<dim3(TT / 32, HH, BB), 256>>>(qkv, y_hi, y_lo);

        gemm_tc2<1, 2><<<dim3(8, 32), 128>>>(
            y_hi, y_lo, wo_hi + (size_t)l*CC*CC, wo_lo + (size_t)l*CC*CC,
            bo + bOff, x, x, nullptr, nullptr, M, CC, CC);

        ln_split<<<M, 128>>>(x, ln2w + bOff, ln2b + bOff, h_hi, h_lo);

        gemm_tc2<2, 4><<<dim3(32, 16), 256>>>(
            h_hi, h_lo, w1_hi + (size_t)l*4*CC*CC, w1_lo + (size_t)l*4*CC*CC,
            b1 + b1Off, nullptr, nullptr, h1_hi, h1_lo, M, 4 * CC, CC);

        gemm_tc2<1, 2><<<dim3(8, 32), 128>>>(
            h1_hi, h1_lo, w2_hi + (size_t)l*4*CC*CC, w2_lo + (size_t)l*4*CC*CC,
            b2 + bOff, x, x, nullptr, nullptr, M, CC, 4 * CC);
    }

    ln_split<<<M, 128>>>(x, lnfw, lnfb, h_hi, h_lo);
    gemm_tc2<0, 4><<<dim3(VV / 64, 16), 256>>>(
        h_hi, h_lo, wh_hi, wh_lo, nullptr, nullptr, out, nullptr, nullptr, M, VV, CC);
}

// round 14
// speedup vs baseline: 1.0634x; 1.0328x over previous
#include <cuda_runtime.h>
#include <cuda_bf16.h>
#include <math.h>
#include <stdint.h>

#define BB 2
#define TT 1024
#define CC 512
#define HH 8
#define DD 64
#define LL 4
#define VV 32000

typedef __nv_bfloat16 bf16;

// ---------------- scratch (no cudaMalloc allowed) ----------------
__device__ float g_x   [BB*TT*CC];
__device__ float g_qkv [BB*TT*3*CC];
__device__ bf16  g_h_hi[BB*TT*CC],  g_h_lo[BB*TT*CC];
__device__ bf16  g_y_hi[BB*TT*CC],  g_y_lo[BB*TT*CC];
__device__ bf16  g_h1_hi[BB*TT*4*CC], g_h1_lo[BB*TT*4*CC];
__device__ bf16 g_wqkv_hi[LL*3*CC*CC], g_wqkv_lo[LL*3*CC*CC];
__device__ bf16 g_wo_hi  [LL*CC*CC],   g_wo_lo  [LL*CC*CC];
__device__ bf16 g_w1_hi  [LL*4*CC*CC], g_w1_lo  [LL*4*CC*CC];
__device__ bf16 g_w2_hi  [LL*4*CC*CC], g_w2_lo  [LL*4*CC*CC];
__device__ bf16 g_wh_hi  [VV*CC],      g_wh_lo  [VV*CC];
__device__ float g_bqkv [LL*3*CC];

// ---------------------------------------------------------------------------
// Unified weight pack (one launch, 7072 tile-blocks).
// ---------------------------------------------------------------------------
__global__ __launch_bounds__(256) void pack_all(
    const float* __restrict__ Wq, const float* __restrict__ Wk,
    const float* __restrict__ Wv, const float* __restrict__ Wo,
    const float* __restrict__ W1, const float* __restrict__ W2,
    const float* __restrict__ Wh,
    bf16* __restrict__ wqkv_hi, bf16* __restrict__ wqkv_lo,
    bf16* __restrict__ wo_hi,   bf16* __restrict__ wo_lo,
    bf16* __restrict__ w1_hi,   bf16* __restrict__ w1_lo,
    bf16* __restrict__ w2_hi,   bf16* __restrict__ w2_lo,
    bf16* __restrict__ wh_hi,   bf16* __restrict__ wh_lo)
{
    const int bid = blockIdx.x;
    const float* W; bf16 *hi, *lo; int K, N, t;

    if (bid < 4 * 768) {
        const int l = bid / 768;
        const int r = bid % 768;
        const size_t w  = (size_t)l * CC * CC;
        const size_t w1 = (size_t)l * 4 * CC * CC;
        if (r < 192) {
            const int which = r / 64;
            t = r % 64;
            W  = (which == 0 ? Wq : which == 1 ? Wk : Wv) + w;
            hi = wqkv_hi + (size_t)l * 3 * CC * CC + (size_t)which * CC * CC;
            lo = wqkv_lo + (size_t)l * 3 * CC * CC + (size_t)which * CC * CC;
            K = CC; N = CC;
        } else if (r < 256) {
            t = r - 192;
            W = Wo + w; hi = wo_hi + w; lo = wo_lo + w;
            K = CC; N = CC;
        } else if (r < 512) {
            t = r - 256;
            W = W1 + w1; hi = w1_hi + w1; lo = w1_lo + w1;
            K = CC; N = 4 * CC;
        } else {
            t = r - 512;
            W = W2 + w1; hi = w2_hi + w1; lo = w2_lo + w1;
            K = 4 * CC; N = CC;
        }
    } else {
        t = bid - 4 * 768;
        W = Wh; hi = wh_hi; lo = wh_lo;
        K = CC; N = VV;
    }

    const int tiles_n = N >> 6;
    const int n0 = (t % tiles_n) << 6;
    const int k0 = (t / tiles_n) << 6;

    __shared__ float tl[64][65];
    const int tid = threadIdx.x;
    #pragma unroll
    for (int i = 0; i < 4; i++) {
        int idx = tid + i * 256;
        int r = idx >> 4, c4 = (idx & 15) << 2;
        float4 v = *(const float4*)&W[(size_t)(k0 + r) * N + n0 + c4];
        tl[r][c4 + 0] = v.x; tl[r][c4 + 1] = v.y;
        tl[r][c4 + 2] = v.z; tl[r][c4 + 3] = v.w;
    }
    __syncthreads();
    const int kc = tid & 7;
    #pragma unroll
    for (int p = 0; p < 2; p++) {
        int nl = (tid >> 3) + p * 32;
        int n = n0 + nl;
        bf16 h8[8], l8[8];
        #pragma unroll
        for (int j = 0; j < 8; j++) {
            float v = tl[kc * 8 + j][nl];
            h8[j] = __float2bfloat16(v);
            l8[j] = __float2bfloat16(v - __bfloat162float(h8[j]));
        }
        *(uint4*)&hi[(size_t)n * K + k0 + kc * 8] = *(uint4*)h8;
        *(uint4*)&lo[(size_t)n * K + k0 + kc * 8] = *(uint4*)l8;
    }
}

__global__ void pack_bqkv(const float* __restrict__ bq, const float* __restrict__ bk,
                          const float* __restrict__ bv, float* __restrict__ out)
{
    int i = blockIdx.x * 256 + threadIdx.x;
    if (i >= LL * 3 * CC) return;
    int l = i / (3 * CC), c = i % (3 * CC);
    float v = (c < CC) ? bq[l * CC + c]
            : (c < 2 * CC) ? bk[l * CC + c - CC] : bv[l * CC + c - 2 * CC];
    out[i] = v;
}

// ---------------------------------------------------------------------------
// Embedding
// ---------------------------------------------------------------------------
__global__ void embed_kernel(const int* __restrict__ idx,
                             const float* __restrict__ tok,
                             const float* __restrict__ pos,
                             float* __restrict__ x)
{
    int i  = blockIdx.x * blockDim.x + threadIdx.x;
    int c4 = (i & 127) << 2;
    int bt = i >> 7;
    int t  = bt & (TT - 1);
    int row = idx[bt];
    float4 a = *(const float4*)&tok[row * CC + c4];
    float4 p = *(const float4*)&pos[t   * CC + c4];
    float4 o;
    o.x = a.x + p.x; o.y = a.y + p.y; o.z = a.z + p.z; o.w = a.w + p.w;
    *(float4*)&x[bt * CC + c4] = o;
}

// ---------------------------------------------------------------------------
// LayerNorm -> split bf16 hi/lo outputs
// ---------------------------------------------------------------------------
__global__ __launch_bounds__(128) void ln_split(const float* __restrict__ x,
                                                const float* __restrict__ w,
                                                const float* __restrict__ b,
                                                bf16* __restrict__ ohi,
                                                bf16* __restrict__ olo)
{
    __shared__ float red[4];
    const int row = blockIdx.x;
    const int tid = threadIdx.x;

    float4 v = *(const float4*)&x[row * CC + tid * 4];
    float s = v.x + v.y + v.z + v.w;
    #pragma unroll
    for (int o = 16; o; o >>= 1) s += __shfl_xor_sync(0xffffffffu, s, o);
    if ((tid & 31) == 0) red[tid >> 5] = s;
    __syncthreads();
    float mean = (red[0] + red[1] + red[2] + red[3]) * (1.0f / CC);

    float d0 = v.x - mean, d1 = v.y - mean, d2 = v.z - mean, d3 = v.w - mean;
    float ss = d0*d0 + d1*d1 + d2*d2 + d3*d3;
    #pragma unroll
    for (int o = 16; o; o >>= 1) ss += __shfl_xor_sync(0xffffffffu, ss, o);
    __syncthreads();
    if ((tid & 31) == 0) red[tid >> 5] = ss;
    __syncthreads();
    float var  = (red[0] + red[1] + red[2] + red[3]) * (1.0f / CC);
    float rstd = rsqrtf(var + 1e-5f);

    float4 wv = *(const float4*)&w[tid * 4];
    float4 bv = *(const float4*)&b[tid * 4];
    float o4[4];
    o4[0] = d0 * rstd * wv.x + bv.x;
    o4[1] = d1 * rstd * wv.y + bv.y;
    o4[2] = d2 * rstd * wv.z + bv.z;
    o4[3] = d3 * rstd * wv.w + bv.w;

    bf16 hi[4], lo[4];
    #pragma unroll
    for (int j = 0; j < 4; j++) {
        hi[j] = __float2bfloat16(o4[j]);
        lo[j] = __float2bfloat16(o4[j] - __bfloat162float(hi[j]));
    }
    *(uint2*)&ohi[row * CC + tid * 4] = *(uint2*)hi;
    *(uint2*)&olo[row * CC + tid * 4] = *(uint2*)lo;
}

// ---------------------------------------------------------------------------
// Tensor-core GEMM, pre-split bf16 operands (hi*hi+hi*lo+lo*hi, fp32 accum).
// Fragment loads via ldmatrix.x4 (was: scalar LDS.32).
// ---------------------------------------------------------------------------
#define SWZ(r) ((((r) >> 1) & 3) << 2)

__device__ __forceinline__ void mma_bf16(float* c, const uint32_t* a, const uint32_t* b)
{
    asm volatile(
        "mma.sync.aligned.m16n8k16.row.col.f32.bf16.bf16.f32 "
        "{%0,%1,%2,%3}, {%4,%5,%6,%7}, {%8,%9}, {%0,%1,%2,%3};"
        : "+f"(c[0]), "+f"(c[1]), "+f"(c[2]), "+f"(c[3])
        : "r"(a[0]), "r"(a[1]), "r"(a[2]), "r"(a[3]), "r"(b[0]), "r"(b[1]));
}

__device__ __forceinline__ void ldsm4(uint32_t* r, uint32_t addr)
{
    asm volatile("ldmatrix.sync.aligned.m8n8.x4.shared.b16 {%0,%1,%2,%3}, [%4];"
                 : "=r"(r[0]), "=r"(r[1]), "=r"(r[2]), "=r"(r[3]) : "r"(addr));
}

__device__ __forceinline__ void cp16(uint32_t dst, const void* src)
{
    asm volatile("cp.async.cg.shared.global [%0], [%1], 16;\n"
                 :: "r"(dst), "l"(src));
}

template<int MODE, int WM>
__global__ __launch_bounds__(WM * 64, (WM == 4) ? 2 : 4) void gemm_tc2(
    const bf16* __restrict__ Ah, const bf16* __restrict__ Al,
    const bf16* __restrict__ Bh, const bf16* __restrict__ Bl,
    const float* __restrict__ bias, const float* __restrict__ resid,
    float* __restrict__ C, bf16* __restrict__ Chi, bf16* __restrict__ Clo,
    int M, int N, int K)
{
    constexpr int BM  = WM * 32;
    constexpr int NT  = WM * 64;
    constexpr int LA  = (WM == 4) ? 9 : 8;
    constexpr int BPT = 512 / NT;

    __shared__ __align__(16) uint32_t As[2][2][BM][16];
    __shared__ __align__(16) uint32_t Bs[2][2][64][16];

    const int tid = threadIdx.x;
    const int lid = tid & 31;
    const int wid = tid >> 5;
    const int warp_m = wid % WM;
    const int warp_n = wid / WM;
    const int bm = blockIdx.y * BM;
    const int bn = blockIdx.x * 64;

    // ---- ldmatrix lane mappings ----
    const int a_row_in = (lid & 7) | (((lid >> 3) & 1) << 3);   // 0..15
    const int a_csel   = lid >> 4;                              // 0/1
    const int b_row_in = lid & 7;
    const int b_csel   = (lid >> 3) & 1;
    const int b_ntsel  = lid >> 4;

    int a_row[2], a_sw[2];
    #pragma unroll
    for (int mt = 0; mt < 2; mt++) {
        a_row[mt] = warp_m * 32 + mt * 16 + a_row_in;
        a_sw[mt]  = (a_row[mt] >> 1) & 3;
    }
    int b_row[2], b_sw[2];
    #pragma unroll
    for (int q = 0; q < 2; q++) {
        b_row[q] = warp_n * 32 + (2 * q + b_ntsel) * 8 + b_row_in;
        b_sw[q]  = (b_row[q] >> 1) & 3;
    }

    const uint32_t as_base = (uint32_t)__cvta_generic_to_shared(&As[0][0][0][0]);
    const uint32_t bs_base = (uint32_t)__cvta_generic_to_shared(&Bs[0][0][0][0]);

    float acc[2][4][4];
    #pragma unroll
    for (int i = 0; i < 2; i++)
        #pragma unroll
        for (int j = 0; j < 4; j++)
            #pragma unroll
            for (int q = 0; q < 4; q++) acc[i][j][q] = 0.0f;

    auto load_stage = [&](int st, int k0) {
        #pragma unroll
        for (int i = 0; i < 4; i++) {
            int id  = tid + i * NT;
            int c   = id & 3;
            int row = (id >> 2) & (BM - 1);
            int hl  = id >> LA;
            const bf16* src = (hl ? Al : Ah) + (size_t)(bm + row) * K + k0 + c * 8;
            uint32_t dst = (uint32_t)__cvta_generic_to_shared(
                &As[st][hl][row][(c ^ ((row >> 1) & 3)) << 2]);
            cp16(dst, src);
        }
        #pragma unroll
        for (int i = 0; i < BPT; i++) {
            int id = tid + i * NT;
            int c  = id & 3;
            int n  = (id >> 2) & 63;
            int hl = id >> 8;
            const bf16* src = (hl ? Bl : Bh) + (size_t)(bn + n) * K + k0 + c * 8;
            uint32_t dst = (uint32_t)__cvta_generic_to_shared(
                &Bs[st][hl][n][(c ^ ((n >> 1) & 3)) << 2]);
            cp16(dst, src);
        }
    };

    const int nst = K / 32;
    load_stage(0, 0);
    asm volatile("cp.async.commit_group;" ::: "memory");
    load_stage(1, 32);
    asm volatile("cp.async.commit_group;" ::: "memory");

    int buf = 0;
    for (int st = 0; st < nst; st++) {
        if (st == nst - 1) asm volatile("cp.async.wait_group 0;" ::: "memory");
        else               asm volatile("cp.async.wait_group 1;" ::: "memory");
        __syncthreads();

        #pragma unroll
        for (int j = 0; j < 2; j++) {      // two k16 chunks
            uint32_t Af[2][2][4];          // [hl][mt][4]
            uint32_t Bf[2][4][2];          // [hl][nt][2]
            #pragma unroll
            for (int mt = 0; mt < 2; mt++)
                #pragma unroll
                for (int hl = 0; hl < 2; hl++) {
                    uint32_t addr = as_base
                        + ((((buf * 2 + hl) * BM + a_row[mt]) * 16) << 2)
                        + (((2 * j + a_csel) ^ a_sw[mt]) << 4);
                    ldsm4(Af[hl][mt], addr);
                }
            #pragma unroll
            for (int q = 0; q < 2; q++)
                #pragma unroll
                for (int hl = 0; hl < 2; hl++) {
                    uint32_t addr = bs_base
                        + ((((buf * 2 + hl) * 64 + b_row[q]) * 16) << 2)
                        + (((2 * j + b_csel) ^ b_sw[q]) << 4);
                    ldsm4(&Bf[hl][2 * q][0], addr);
                }
            #pragma unroll
            for (int mt = 0; mt < 2; mt++)
                #pragma unroll
                for (int nt = 0; nt < 4; nt++) {
                    mma_bf16(acc[mt][nt], Af[0][mt], Bf[0][nt]);   // hi*hi
                    mma_bf16(acc[mt][nt], Af[0][mt], Bf[1][nt]);   // hi*lo
                    mma_bf16(acc[mt][nt], Af[1][mt], Bf[0][nt]);   // lo*hi
                }
        }

        if (st + 2 < nst) {
            __syncthreads();
            load_stage(buf, (st + 2) * 32);
            asm volatile("cp.async.commit_group;" ::: "memory");
        }
        buf ^= 1;
    }

    #pragma unroll
    for (int mt = 0; mt < 2; mt++) {
        #pragma unroll
        for (int nt = 0; nt < 4; nt++) {
            int r0 = bm + warp_m * 32 + mt * 16 + (lid >> 2);
            int cc = bn + warp_n * 32 + nt * 8 + ((lid & 3) << 1);
            float2 bb = make_float2(0.0f, 0.0f);
            if (bias) bb = *(const float2*)(bias + cc);
            float* a4 = acc[mt][nt];
            #pragma unroll
            for (int half = 0; half < 2; half++) {
                int row = r0 + half * 8;
                float o0 = a4[half * 2 + 0] + bb.x;
                float o1 = a4[half * 2 + 1] + bb.y;
                if (MODE == 1) {
                    float2 rr = *(const float2*)(resid + (size_t)row * N + cc);
                    o0 += rr.x; o1 += rr.y;
                }
                if (MODE == 2) {
                    o0 = 0.5f * o0 * (1.0f + erff(o0 * 0.70710678118654752f));
                    o1 = 0.5f * o1 * (1.0f + erff(o1 * 0.70710678118654752f));
                    __nv_bfloat162 h2, l2;
                    h2.x = __float2bfloat16(o0);
                    h2.y = __float2bfloat16(o1);
                    l2.x = __float2bfloat16(o0 - __bfloat162float(h2.x));
                    l2.y = __float2bfloat16(o1 - __bfloat162float(h2.y));
                    *(__nv_bfloat162*)(Chi + (size_t)row * N + cc) = h2;
                    *(__nv_bfloat162*)(Clo + (size_t)row * N + cc) = l2;
                } else {
                    *(float2*)(C + (size_t)row * N + cc) = make_float2(o0, o1);
                }
            }
        }
    }
}

// ---------------------------------------------------------------------------
// Flash attention (fp32, causal), vectorized LDS.128 with XOR swizzles.
// ---------------------------------------------------------------------------
__global__ __launch_bounds__(256) void attn_kernel(
    const float* __restrict__ QKV, bf16* __restrict__ Yh, bf16* __restrict__ Yl)
{
    const int qt = blockIdx.x;
    const int h  = blockIdx.y;
    const int b  = blockIdx.z;

    __shared__ float Qs[32][64];
    __shared__ float Ks[64][64];
    __shared__ float Vs[64][64];
    __shared__ float Ps[32][64];

    const int tid = threadIdx.x;
    const int sb  = tid & 7;
    const int r   = tid >> 3;
    const int qg  = qt * 32 + r;
    const int ST  = 3 * CC;

    for (int i = tid; i < 512; i += 256) {
        int rr = i >> 4, c4 = i & 15;
        ((float4*)Qs)[rr * 16 + (c4 ^ (rr & 7))] =
            *(const float4*)&QKV[(size_t)(b * TT + qt * 32 + rr) * ST + h * DD + c4 * 4];
    }

    float m = -1e30f, l = 0.0f;
    float4 acc0 = make_float4(0.f, 0.f, 0.f, 0.f);
    float4 acc1 = make_float4(0.f, 0.f, 0.f, 0.f);
    const int nkt = (qt >> 1) + 1;

    for (int kt = 0; kt < nkt; kt++) {
        __syncthreads();
        for (int i = tid; i < 1024; i += 256) {
            int rr = i >> 4, c4 = i & 15;
            size_t g = (size_t)(b * TT + kt * 64 + rr) * ST + h * DD + c4 * 4;
            int sw = rr * 16 + (c4 ^ ((rr >> 2) & 7));
            ((float4*)Ks)[sw] = *(const float4*)&QKV[g + CC];
            ((float4*)Vs)[sw] = *(const float4*)&QKV[g + 2 * CC];
        }
        __syncthreads();

        float sv[8];
        #pragma unroll
        for (int e = 0; e < 8; e++) sv[e] = 0.0f;
        #pragma unroll 4
        for (int d4 = 0; d4 < 16; d4++) {
            float4 qv = ((float4*)Qs)[r * 16 + (d4 ^ (r & 7))];
            #pragma unroll
            for (int half = 0; half < 2; half++)
                #pragma unroll
                for (int jj = 0; jj < 4; jj++) {
                    int key = half * 32 + sb * 4 + jj;
                    float4 kv = ((float4*)Ks)[key * 16 + (d4 ^ sb)];
                    sv[half * 4 + jj] += qv.x * kv.x + qv.y * kv.y
                                       + qv.z * kv.z + qv.w * kv.w;
                }
        }

        float tmax = -1e30f;
        #pragma unroll
        for (int e = 0; e < 8; e++) {
            int key = (e >> 2) * 32 + sb * 4 + (e & 3);
            int kgl = kt * 64 + key;
            sv[e] = (kgl <= qg) ? sv[e] * 0.125f : -1e30f;
            tmax = fmaxf(tmax, sv[e]);
        }
        #pragma unroll
        for (int o = 4; o; o >>= 1)
            tmax = fmaxf(tmax, __shfl_xor_sync(0xffffffffu, tmax, o, 8));

        float m_new = fmaxf(m, tmax);
        float psum = 0.0f;
        #pragma unroll
        for (int e = 0; e < 8; e++) {
            int key = (e >> 2) * 32 + sb * 4 + (e & 3);
            float p = __expf(sv[e] - m_new);
            Ps[r][key ^ ((r & 3) << 3)] = p;
            psum += p;
        }
        #pragma unroll
        for (int o = 4; o; o >>= 1)
            psum += __shfl_xor_sync(0xffffffffu, psum, o, 8);

        float alpha = __expf(m - m_new);
        m = m_new;
        l = l * alpha + psum;
        acc0.x *= alpha; acc0.y *= alpha; acc0.z *= alpha; acc0.w *= alpha;
        acc1.x *= alpha; acc1.y *= alpha; acc1.z *= alpha; acc1.w *= alpha;
        __syncwarp();

        #pragma unroll 4
        for (int s = 0; s < 64; s++) {
            float p = Ps[r][s ^ ((r & 3) << 3)];
            int swz = (s >> 2) & 7;
            float4 v0 = ((float4*)Vs)[s * 16 + (sb ^ swz)];
            float4 v1 = ((float4*)Vs)[s * 16 + ((sb + 8) ^ swz)];
            acc0.x += p * v0.x; acc0.y += p * v0.y;
            acc0.z += p * v0.z; acc0.w += p * v0.w;
            acc1.x += p * v1.x; acc1.y += p * v1.y;
            acc1.z += p * v1.z; acc1.w += p * v1.w;
        }
        __syncwarp();
    }

    const float inv_l = 1.0f / l;
    const size_t o = (size_t)(b * TT + qg) * CC + h * DD;
    float vv[8] = {acc0.x * inv_l, acc0.y * inv_l, acc0.z * inv_l, acc0.w * inv_l,
                   acc1.x * inv_l, acc1.y * inv_l, acc1.z * inv_l, acc1.w * inv_l};
    bf16 hh[8], ll[8];
    #pragma unroll
    for (int j = 0; j < 8; j++) {
        hh[j] = __float2bfloat16(vv[j]);
        ll[j] = __float2bfloat16(vv[j] - __bfloat162float(hh[j]));
    }
    *(uint2*)&Yh[o + sb * 4]      = *(uint2*)&hh[0];
    *(uint2*)&Yh[o + 32 + sb * 4] = *(uint2*)&hh[4];
    *(uint2*)&Yl[o + sb * 4]      = *(uint2*)&ll[0];
    *(uint2*)&Yl[o + 32 + sb * 4] = *(uint2*)&ll[4];
}

// ---------------------------------------------------------------------------
// Launch
// ---------------------------------------------------------------------------
extern "C" void kernel_launch(void* const* d_in, const int* in_sizes, int n_in,
                              void* d_out, int out_size)
{
    const int*   idx   = (const int*)  d_in[0];
    const float* tok   = (const float*)d_in[1];
    const float* pos   = (const float*)d_in[2];
    const float* ln1w  = (const float*)d_in[3];
    const float* ln1b  = (const float*)d_in[4];
    const float* Wq    = (const float*)d_in[5];
    const float* bq    = (const float*)d_in[6];
    const float* Wk    = (const float*)d_in[7];
    const float* bk    = (const float*)d_in[8];
    const float* Wv    = (const float*)d_in[9];
    const float* bv    = (const float*)d_in[10];
    const float* Wo    = (const float*)d_in[11];
    const float* bo    = (const float*)d_in[12];
    const float* ln2w  = (const float*)d_in[13];
    const float* ln2b  = (const float*)d_in[14];
    const float* W1    = (const float*)d_in[15];
    const float* b1    = (const float*)d_in[16];
    const float* W2    = (const float*)d_in[17];
    const float* b2    = (const float*)d_in[18];
    const float* lnfw  = (const float*)d_in[19];
    const float* lnfb  = (const float*)d_in[20];
    const float* Whead = (const float*)d_in[21];
    float* out = (float*)d_out;

    float *x, *qkv, *bqkv;
    bf16 *h_hi, *h_lo, *y_hi, *y_lo, *h1_hi, *h1_lo;
    bf16 *wqkv_hi, *wqkv_lo, *wo_hi, *wo_lo, *w1_hi, *w1_lo, *w2_hi, *w2_lo, *wh_hi, *wh_lo;
    cudaGetSymbolAddress((void**)&x,     g_x);
    cudaGetSymbolAddress((void**)&qkv,   g_qkv);
    cudaGetSymbolAddress((void**)&bqkv,  g_bqkv);
    cudaGetSymbolAddress((void**)&h_hi,  g_h_hi);
    cudaGetSymbolAddress((void**)&h_lo,  g_h_lo);
    cudaGetSymbolAddress((void**)&y_hi,  g_y_hi);
    cudaGetSymbolAddress((void**)&y_lo,  g_y_lo);
    cudaGetSymbolAddress((void**)&h1_hi, g_h1_hi);
    cudaGetSymbolAddress((void**)&h1_lo, g_h1_lo);
    cudaGetSymbolAddress((void**)&wqkv_hi, g_wqkv_hi);
    cudaGetSymbolAddress((void**)&wqkv_lo, g_wqkv_lo);
    cudaGetSymbolAddress((void**)&wo_hi,   g_wo_hi);
    cudaGetSymbolAddress((void**)&wo_lo,   g_wo_lo);
    cudaGetSymbolAddress((void**)&w1_hi,   g_w1_hi);
    cudaGetSymbolAddress((void**)&w1_lo,   g_w1_lo);
    cudaGetSymbolAddress((void**)&w2_hi,   g_w2_hi);
    cudaGetSymbolAddress((void**)&w2_lo,   g_w2_lo);
    cudaGetSymbolAddress((void**)&wh_hi,   g_wh_hi);
    cudaGetSymbolAddress((void**)&wh_lo,   g_wh_lo);

    const int M = BB * TT;

    pack_all<<<4 * 768 + (VV / 64) * (CC / 64), 256>>>(
        Wq, Wk, Wv, Wo, W1, W2, Whead,
        wqkv_hi, wqkv_lo, wo_hi, wo_lo, w1_hi, w1_lo, w2_hi, w2_lo, wh_hi, wh_lo);
    pack_bqkv<<<(LL * 3 * CC + 255) / 256, 256>>>(bq, bk, bv, bqkv);
    embed_kernel<<<(M * CC / 4 + 255) / 256, 256>>>(idx, tok, pos, x);

    for (int l = 0; l < LL; l++) {
        const size_t bOff  = (size_t)l * CC;
        const size_t b1Off = (size_t)l * 4 * CC;

        ln_split<<<M, 128>>>(x, ln1w + bOff, ln1b + bOff, h_hi, h_lo);

        gemm_tc2<0, 4><<<dim3(24, 16), 256>>>(
            h_hi, h_lo, wqkv_hi + (size_t)l*3*CC*CC, wqkv_lo + (size_t)l*3*CC*CC,
            bqkv + (size_t)l*3*CC, nullptr, qkv, nullptr, nullptr, M, 3 * CC, CC);

        attn_kernel<<<dim3(TT / 32, HH, BB), 256>>>(qkv, y_hi, y_lo);

        gemm_tc2<1, 2><<<dim3(8, 32), 128>>>(
            y_hi, y_lo, wo_hi + (size_t)l*CC*CC, wo_lo + (size_t)l*CC*CC,
            bo + bOff, x, x, nullptr, nullptr, M, CC, CC);

        ln_split<<<M, 128>>>(x, ln2w + bOff, ln2b + bOff, h_hi, h_lo);

        gemm_tc2<2, 4><<<dim3(32, 16), 256>>>(
            h_hi, h_lo, w1_hi + (size_t)l*4*CC*CC, w1_lo + (size_t)l*4*CC*CC,
            b1 + b1Off, nullptr, nullptr, h1_hi, h1_lo, M, 4 * CC, CC);

        gemm_tc2<1, 2><<<dim3(8, 32), 128>>>(
            h1_hi, h1_lo, w2_hi + (size_t)l*4*CC*CC, w2_lo + (size_t)l*4*CC*CC,
            b2 + bOff, x, x, nullptr, nullptr, M, CC, 4 * CC);
    }

    ln_split<<<M, 128>>>(x, lnfw, lnfb, h_hi, h_lo);
    gemm_tc2<0, 4><<<dim3(VV / 64, 16), 256>>>(
        h_hi, h_lo, wh_hi, wh_lo, nullptr, nullptr, out, nullptr, nullptr, M, VV, CC);
}

// round 15
// speedup vs baseline: 1.0661x; 1.0026x over previous
#include <cuda_runtime.h>
#include <cuda_bf16.h>
#include <math.h>
#include <stdint.h>

#define BB 2
#define TT 1024
#define CC 512
#define HH 8
#define DD 64
#define LL 4
#define VV 32000

typedef __nv_bfloat16 bf16;

// ---------------- scratch (no cudaMalloc allowed) ----------------
__device__ float g_x   [BB*TT*CC];
__device__ float g_qkv [BB*TT*3*CC];
__device__ bf16  g_h_hi[BB*TT*CC],  g_h_lo[BB*TT*CC];
__device__ bf16  g_y_hi[BB*TT*CC],  g_y_lo[BB*TT*CC];
__device__ bf16  g_h1_hi[BB*TT*4*CC], g_h1_lo[BB*TT*4*CC];
__device__ bf16 g_wqkv_hi[LL*3*CC*CC], g_wqkv_lo[LL*3*CC*CC];
__device__ bf16 g_wo_hi  [LL*CC*CC],   g_wo_lo  [LL*CC*CC];
__device__ bf16 g_w1_hi  [LL*4*CC*CC], g_w1_lo  [LL*4*CC*CC];
__device__ bf16 g_w2_hi  [LL*4*CC*CC], g_w2_lo  [LL*4*CC*CC];
__device__ bf16 g_wh_hi  [VV*CC],      g_wh_lo  [VV*CC];
__device__ float g_bqkv [LL*3*CC];

// ---------------------------------------------------------------------------
// Unified weight pack (one launch, 7072 tile-blocks).
// ---------------------------------------------------------------------------
__global__ __launch_bounds__(256) void pack_all(
    const float* __restrict__ Wq, const float* __restrict__ Wk,
    const float* __restrict__ Wv, const float* __restrict__ Wo,
    const float* __restrict__ W1, const float* __restrict__ W2,
    const float* __restrict__ Wh,
    bf16* __restrict__ wqkv_hi, bf16* __restrict__ wqkv_lo,
    bf16* __restrict__ wo_hi,   bf16* __restrict__ wo_lo,
    bf16* __restrict__ w1_hi,   bf16* __restrict__ w1_lo,
    bf16* __restrict__ w2_hi,   bf16* __restrict__ w2_lo,
    bf16* __restrict__ wh_hi,   bf16* __restrict__ wh_lo)
{
    const int bid = blockIdx.x;
    const float* W; bf16 *hi, *lo; int K, N, t;

    if (bid < 4 * 768) {
        const int l = bid / 768;
        const int r = bid % 768;
        const size_t w  = (size_t)l * CC * CC;
        const size_t w1 = (size_t)l * 4 * CC * CC;
        if (r < 192) {
            const int which = r / 64;
            t = r % 64;
            W  = (which == 0 ? Wq : which == 1 ? Wk : Wv) + w;
            hi = wqkv_hi + (size_t)l * 3 * CC * CC + (size_t)which * CC * CC;
            lo = wqkv_lo + (size_t)l * 3 * CC * CC + (size_t)which * CC * CC;
            K = CC; N = CC;
        } else if (r < 256) {
            t = r - 192;
            W = Wo + w; hi = wo_hi + w; lo = wo_lo + w;
            K = CC; N = CC;
        } else if (r < 512) {
            t = r - 256;
            W = W1 + w1; hi = w1_hi + w1; lo = w1_lo + w1;
            K = CC; N = 4 * CC;
        } else {
            t = r - 512;
            W = W2 + w1; hi = w2_hi + w1; lo = w2_lo + w1;
            K = 4 * CC; N = CC;
        }
    } else {
        t = bid - 4 * 768;
        W = Wh; hi = wh_hi; lo = wh_lo;
        K = CC; N = VV;
    }

    const int tiles_n = N >> 6;
    const int n0 = (t % tiles_n) << 6;
    const int k0 = (t / tiles_n) << 6;

    __shared__ float tl[64][65];
    const int tid = threadIdx.x;
    #pragma unroll
    for (int i = 0; i < 4; i++) {
        int idx = tid + i * 256;
        int r = idx >> 4, c4 = (idx & 15) << 2;
        float4 v = *(const float4*)&W[(size_t)(k0 + r) * N + n0 + c4];
        tl[r][c4 + 0] = v.x; tl[r][c4 + 1] = v.y;
        tl[r][c4 + 2] = v.z; tl[r][c4 + 3] = v.w;
    }
    __syncthreads();
    const int kc = tid & 7;
    #pragma unroll
    for (int p = 0; p < 2; p++) {
        int nl = (tid >> 3) + p * 32;
        int n = n0 + nl;
        bf16 h8[8], l8[8];
        #pragma unroll
        for (int j = 0; j < 8; j++) {
            float v = tl[kc * 8 + j][nl];
            h8[j] = __float2bfloat16(v);
            l8[j] = __float2bfloat16(v - __bfloat162float(h8[j]));
        }
        *(uint4*)&hi[(size_t)n * K + k0 + kc * 8] = *(uint4*)h8;
        *(uint4*)&lo[(size_t)n * K + k0 + kc * 8] = *(uint4*)l8;
    }
}

__global__ void pack_bqkv(const float* __restrict__ bq, const float* __restrict__ bk,
                          const float* __restrict__ bv, float* __restrict__ out)
{
    int i = blockIdx.x * 256 + threadIdx.x;
    if (i >= LL * 3 * CC) return;
    int l = i / (3 * CC), c = i % (3 * CC);
    float v = (c < CC) ? bq[l * CC + c]
            : (c < 2 * CC) ? bk[l * CC + c - CC] : bv[l * CC + c - 2 * CC];
    out[i] = v;
}

// ---------------------------------------------------------------------------
// Embedding
// ---------------------------------------------------------------------------
__global__ void embed_kernel(const int* __restrict__ idx,
                             const float* __restrict__ tok,
                             const float* __restrict__ pos,
                             float* __restrict__ x)
{
    int i  = blockIdx.x * blockDim.x + threadIdx.x;
    int c4 = (i & 127) << 2;
    int bt = i >> 7;
    int t  = bt & (TT - 1);
    int row = idx[bt];
    float4 a = *(const float4*)&tok[row * CC + c4];
    float4 p = *(const float4*)&pos[t   * CC + c4];
    float4 o;
    o.x = a.x + p.x; o.y = a.y + p.y; o.z = a.z + p.z; o.w = a.w + p.w;
    *(float4*)&x[bt * CC + c4] = o;
}

// ---------------------------------------------------------------------------
// LayerNorm -> split bf16 hi/lo outputs
// ---------------------------------------------------------------------------
__global__ __launch_bounds__(128) void ln_split(const float* __restrict__ x,
                                                const float* __restrict__ w,
                                                const float* __restrict__ b,
                                                bf16* __restrict__ ohi,
                                                bf16* __restrict__ olo)
{
    __shared__ float red[4];
    const int row = blockIdx.x;
    const int tid = threadIdx.x;

    float4 v = *(const float4*)&x[row * CC + tid * 4];
    float s = v.x + v.y + v.z + v.w;
    #pragma unroll
    for (int o = 16; o; o >>= 1) s += __shfl_xor_sync(0xffffffffu, s, o);
    if ((tid & 31) == 0) red[tid >> 5] = s;
    __syncthreads();
    float mean = (red[0] + red[1] + red[2] + red[3]) * (1.0f / CC);

    float d0 = v.x - mean, d1 = v.y - mean, d2 = v.z - mean, d3 = v.w - mean;
    float ss = d0*d0 + d1*d1 + d2*d2 + d3*d3;
    #pragma unroll
    for (int o = 16; o; o >>= 1) ss += __shfl_xor_sync(0xffffffffu, ss, o);
    __syncthreads();
    if ((tid & 31) == 0) red[tid >> 5] = ss;
    __syncthreads();
    float var  = (red[0] + red[1] + red[2] + red[3]) * (1.0f / CC);
    float rstd = rsqrtf(var + 1e-5f);

    float4 wv = *(const float4*)&w[tid * 4];
    float4 bv = *(const float4*)&b[tid * 4];
    float o4[4];
    o4[0] = d0 * rstd * wv.x + bv.x;
    o4[1] = d1 * rstd * wv.y + bv.y;
    o4[2] = d2 * rstd * wv.z + bv.z;
    o4[3] = d3 * rstd * wv.w + bv.w;

    bf16 hi[4], lo[4];
    #pragma unroll
    for (int j = 0; j < 4; j++) {
        hi[j] = __float2bfloat16(o4[j]);
        lo[j] = __float2bfloat16(o4[j] - __bfloat162float(hi[j]));
    }
    *(uint2*)&ohi[row * CC + tid * 4] = *(uint2*)hi;
    *(uint2*)&olo[row * CC + tid * 4] = *(uint2*)lo;
}

// ---------------------------------------------------------------------------
// Tensor-core GEMM, pre-split bf16 operands (hi*hi+hi*lo+lo*hi, fp32 accum).
// ldmatrix fragment loads; BN=64 or 128 (head GEMM uses 128 for A-reuse).
// B fragments loaded per-hl serially to bound register pressure.
// ---------------------------------------------------------------------------
__device__ __forceinline__ void mma_bf16(float* c, const uint32_t* a, const uint32_t* b)
{
    asm volatile(
        "mma.sync.aligned.m16n8k16.row.col.f32.bf16.bf16.f32 "
        "{%0,%1,%2,%3}, {%4,%5,%6,%7}, {%8,%9}, {%0,%1,%2,%3};"
        : "+f"(c[0]), "+f"(c[1]), "+f"(c[2]), "+f"(c[3])
        : "r"(a[0]), "r"(a[1]), "r"(a[2]), "r"(a[3]), "r"(b[0]), "r"(b[1]));
}

__device__ __forceinline__ void ldsm4(uint32_t* r, uint32_t addr)
{
    asm volatile("ldmatrix.sync.aligned.m8n8.x4.shared.b16 {%0,%1,%2,%3}, [%4];"
                 : "=r"(r[0]), "=r"(r[1]), "=r"(r[2]), "=r"(r[3]) : "r"(addr));
}

__device__ __forceinline__ void cp16(uint32_t dst, const void* src)
{
    asm volatile("cp.async.cg.shared.global [%0], [%1], 16;\n"
                 :: "r"(dst), "l"(src));
}

template<int MODE, int WM, int BN>
__global__ __launch_bounds__(WM * 64, (BN == 128) ? 1 : ((WM == 4) ? 2 : 4))
void gemm_tc2(
    const bf16* __restrict__ Ah, const bf16* __restrict__ Al,
    const bf16* __restrict__ Bh, const bf16* __restrict__ Bl,
    const float* __restrict__ bias, const float* __restrict__ resid,
    float* __restrict__ C, bf16* __restrict__ Chi, bf16* __restrict__ Clo,
    int M, int N, int K)
{
    constexpr int BM  = WM * 32;
    constexpr int NT  = WM * 64;
    constexpr int LA  = (WM == 4) ? 9 : 8;     // A: log2(BM*4) chunks per hl
    constexpr int NTT = BN / 16;               // n-subtiles (8 wide) per warp_n
    constexpr int NQ  = NTT / 2;               // ldsm nt-pairs
    constexpr int BCH = BN * 8 / NT;           // B chunks per thread per stage

    __shared__ __align__(16) uint32_t As[2][2][BM][16];
    __shared__ __align__(16) uint32_t Bs[2][2][BN][16];

    const int tid = threadIdx.x;
    const int lid = tid & 31;
    const int wid = tid >> 5;
    const int warp_m = wid % WM;
    const int warp_n = wid / WM;
    const int bm = blockIdx.y * BM;
    const int bn = blockIdx.x * BN;

    // ---- ldmatrix lane mappings ----
    const int a_row_in = (lid & 7) | (((lid >> 3) & 1) << 3);
    const int a_csel   = lid >> 4;
    const int b_row_in = lid & 7;
    const int b_csel   = (lid >> 3) & 1;
    const int b_ntsel  = lid >> 4;

    int a_row[2], a_sw[2];
    #pragma unroll
    for (int mt = 0; mt < 2; mt++) {
        a_row[mt] = warp_m * 32 + mt * 16 + a_row_in;
        a_sw[mt]  = (a_row[mt] >> 1) & 3;
    }
    int b_row[NQ], b_sw[NQ];
    #pragma unroll
    for (int q = 0; q < NQ; q++) {
        b_row[q] = warp_n * (BN / 2) + (2 * q + b_ntsel) * 8 + b_row_in;
        b_sw[q]  = (b_row[q] >> 1) & 3;
    }

    const uint32_t as_base = (uint32_t)__cvta_generic_to_shared(&As[0][0][0][0]);
    const uint32_t bs_base = (uint32_t)__cvta_generic_to_shared(&Bs[0][0][0][0]);

    float acc[2][NTT][4];
    #pragma unroll
    for (int i = 0; i < 2; i++)
        #pragma unroll
        for (int j = 0; j < NTT; j++)
            #pragma unroll
            for (int q = 0; q < 4; q++) acc[i][j][q] = 0.0f;

    auto load_stage = [&](int st, int k0) {
        #pragma unroll
        for (int i = 0; i < 4; i++) {
            int id  = tid + i * NT;
            int c   = id & 3;
            int row = (id >> 2) & (BM - 1);
            int hl  = id >> LA;
            const bf16* src = (hl ? Al : Ah) + (size_t)(bm + row) * K + k0 + c * 8;
            uint32_t dst = (uint32_t)__cvta_generic_to_shared(
                &As[st][hl][row][(c ^ ((row >> 1) & 3)) << 2]);
            cp16(dst, src);
        }
        #pragma unroll
        for (int i = 0; i < BCH; i++) {
            int id = tid + i * NT;
            int c  = id & 3;
            int n  = (id >> 2) & (BN - 1);
            int hl = id / (BN * 4);
            const bf16* src = (hl ? Bl : Bh) + (size_t)(bn + n) * K + k0 + c * 8;
            uint32_t dst = (uint32_t)__cvta_generic_to_shared(
                &Bs[st][hl][n][(c ^ ((n >> 1) & 3)) << 2]);
            cp16(dst, src);
        }
    };

    const int nst = K / 32;
    load_stage(0, 0);
    asm volatile("cp.async.commit_group;" ::: "memory");
    load_stage(1, 32);
    asm volatile("cp.async.commit_group;" ::: "memory");

    int buf = 0;
    for (int st = 0; st < nst; st++) {
        if (st == nst - 1) asm volatile("cp.async.wait_group 0;" ::: "memory");
        else               asm volatile("cp.async.wait_group 1;" ::: "memory");
        __syncthreads();

        #pragma unroll
        for (int j = 0; j < 2; j++) {      // two k16 chunks
            uint32_t Af[2][2][4];          // [hl][mt][4]
            #pragma unroll
            for (int mt = 0; mt < 2; mt++)
                #pragma unroll
                for (int hl = 0; hl < 2; hl++) {
                    uint32_t addr = as_base
                        + ((((buf * 2 + hl) * BM + a_row[mt]) * 16) << 2)
                        + (((2 * j + a_csel) ^ a_sw[mt]) << 4);
                    ldsm4(Af[hl][mt], addr);
                }
            #pragma unroll
            for (int bhl = 0; bhl < 2; bhl++) {
                uint32_t Bf[NTT][2];
                #pragma unroll
                for (int q = 0; q < NQ; q++) {
                    uint32_t addr = bs_base
                        + ((((buf * 2 + bhl) * BN + b_row[q]) * 16) << 2)
                        + (((2 * j + b_csel) ^ b_sw[q]) << 4);
                    ldsm4(&Bf[2 * q][0], addr);
                }
                #pragma unroll
                for (int mt = 0; mt < 2; mt++)
                    #pragma unroll
                    for (int nt = 0; nt < NTT; nt++) {
                        mma_bf16(acc[mt][nt], Af[0][mt], Bf[nt]);      // hi*B
                        if (bhl == 0)
                            mma_bf16(acc[mt][nt], Af[1][mt], Bf[nt]);  // lo*hi
                    }
            }
        }

        if (st + 2 < nst) {
            __syncthreads();
            load_stage(buf, (st + 2) * 32);
            asm volatile("cp.async.commit_group;" ::: "memory");
        }
        buf ^= 1;
    }

    #pragma unroll
    for (int mt = 0; mt < 2; mt++) {
        #pragma unroll
        for (int nt = 0; nt < NTT; nt++) {
            int r0 = bm + warp_m * 32 + mt * 16 + (lid >> 2);
            int cc = bn + warp_n * (BN / 2) + nt * 8 + ((lid & 3) << 1);
            float2 bb = make_float2(0.0f, 0.0f);
            if (bias) bb = *(const float2*)(bias + cc);
            float* a4 = acc[mt][nt];
            #pragma unroll
            for (int half = 0; half < 2; half++) {
                int row = r0 + half * 8;
                float o0 = a4[half * 2 + 0] + bb.x;
                float o1 = a4[half * 2 + 1] + bb.y;
                if (MODE == 1) {
                    float2 rr = *(const float2*)(resid + (size_t)row * N + cc);
                    o0 += rr.x; o1 += rr.y;
                }
                if (MODE == 2) {
                    o0 = 0.5f * o0 * (1.0f + erff(o0 * 0.70710678118654752f));
                    o1 = 0.5f * o1 * (1.0f + erff(o1 * 0.70710678118654752f));
                    __nv_bfloat162 h2, l2;
                    h2.x = __float2bfloat16(o0);
                    h2.y = __float2bfloat16(o1);
                    l2.x = __float2bfloat16(o0 - __bfloat162float(h2.x));
                    l2.y = __float2bfloat16(o1 - __bfloat162float(h2.y));
                    *(__nv_bfloat162*)(Chi + (size_t)row * N + cc) = h2;
                    *(__nv_bfloat162*)(Clo + (size_t)row * N + cc) = l2;
                } else {
                    *(float2*)(C + (size_t)row * N + cc) = make_float2(o0, o1);
                }
            }
        }
    }
}

// ---------------------------------------------------------------------------
// Flash attention (fp32, causal), vectorized LDS.128 with XOR swizzles.
// ---------------------------------------------------------------------------
__global__ __launch_bounds__(256) void attn_kernel(
    const float* __restrict__ QKV, bf16* __restrict__ Yh, bf16* __restrict__ Yl)
{
    const int qt = blockIdx.x;
    const int h  = blockIdx.y;
    const int b  = blockIdx.z;

    __shared__ float Qs[32][64];
    __shared__ float Ks[64][64];
    __shared__ float Vs[64][64];
    __shared__ float Ps[32][64];

    const int tid = threadIdx.x;
    const int sb  = tid & 7;
    const int r   = tid >> 3;
    const int qg  = qt * 32 + r;
    const int ST  = 3 * CC;

    for (int i = tid; i < 512; i += 256) {
        int rr = i >> 4, c4 = i & 15;
        ((float4*)Qs)[rr * 16 + (c4 ^ (rr & 7))] =
            *(const float4*)&QKV[(size_t)(b * TT + qt * 32 + rr) * ST + h * DD + c4 * 4];
    }

    float m = -1e30f, l = 0.0f;
    float4 acc0 = make_float4(0.f, 0.f, 0.f, 0.f);
    float4 acc1 = make_float4(0.f, 0.f, 0.f, 0.f);
    const int nkt = (qt >> 1) + 1;

    for (int kt = 0; kt < nkt; kt++) {
        __syncthreads();
        for (int i = tid; i < 1024; i += 256) {
            int rr = i >> 4, c4 = i & 15;
            size_t g = (size_t)(b * TT + kt * 64 + rr) * ST + h * DD + c4 * 4;
            int sw = rr * 16 + (c4 ^ ((rr >> 2) & 7));
            ((float4*)Ks)[sw] = *(const float4*)&QKV[g + CC];
            ((float4*)Vs)[sw] = *(const float4*)&QKV[g + 2 * CC];
        }
        __syncthreads();

        float sv[8];
        #pragma unroll
        for (int e = 0; e < 8; e++) sv[e] = 0.0f;
        #pragma unroll 4
        for (int d4 = 0; d4 < 16; d4++) {
            float4 qv = ((float4*)Qs)[r * 16 + (d4 ^ (r & 7))];
            #pragma unroll
            for (int half = 0; half < 2; half++)
                #pragma unroll
                for (int jj = 0; jj < 4; jj++) {
                    int key = half * 32 + sb * 4 + jj;
                    float4 kv = ((float4*)Ks)[key * 16 + (d4 ^ sb)];
                    sv[half * 4 + jj] += qv.x * kv.x + qv.y * kv.y
                                       + qv.z * kv.z + qv.w * kv.w;
                }
        }

        float tmax = -1e30f;
        #pragma unroll
        for (int e = 0; e < 8; e++) {
            int key = (e >> 2) * 32 + sb * 4 + (e & 3);
            int kgl = kt * 64 + key;
            sv[e] = (kgl <= qg) ? sv[e] * 0.125f : -1e30f;
            tmax = fmaxf(tmax, sv[e]);
        }
        #pragma unroll
        for (int o = 4; o; o >>= 1)
            tmax = fmaxf(tmax, __shfl_xor_sync(0xffffffffu, tmax, o, 8));

        float m_new = fmaxf(m, tmax);
        float psum = 0.0f;
        #pragma unroll
        for (int e = 0; e < 8; e++) {
            int key = (e >> 2) * 32 + sb * 4 + (e & 3);
            float p = __expf(sv[e] - m_new);
            Ps[r][key ^ ((r & 3) << 3)] = p;
            psum += p;
        }
        #pragma unroll
        for (int o = 4; o; o >>= 1)
            psum += __shfl_xor_sync(0xffffffffu, psum, o, 8);

        float alpha = __expf(m - m_new);
        m = m_new;
        l = l * alpha + psum;
        acc0.x *= alpha; acc0.y *= alpha; acc0.z *= alpha; acc0.w *= alpha;
        acc1.x *= alpha; acc1.y *= alpha; acc1.z *= alpha; acc1.w *= alpha;
        __syncwarp();

        #pragma unroll 4
        for (int s = 0; s < 64; s++) {
            float p = Ps[r][s ^ ((r & 3) << 3)];
            int swz = (s >> 2) & 7;
            float4 v0 = ((float4*)Vs)[s * 16 + (sb ^ swz)];
            float4 v1 = ((float4*)Vs)[s * 16 + ((sb + 8) ^ swz)];
            acc0.x += p * v0.x; acc0.y += p * v0.y;
            acc0.z += p * v0.z; acc0.w += p * v0.w;
            acc1.x += p * v1.x; acc1.y += p * v1.y;
            acc1.z += p * v1.z; acc1.w += p * v1.w;
        }
        __syncwarp();
    }

    const float inv_l = 1.0f / l;
    const size_t o = (size_t)(b * TT + qg) * CC + h * DD;
    float vv[8] = {acc0.x * inv_l, acc0.y * inv_l, acc0.z * inv_l, acc0.w * inv_l,
                   acc1.x * inv_l, acc1.y * inv_l, acc1.z * inv_l, acc1.w * inv_l};
    bf16 hh[8], ll[8];
    #pragma unroll
    for (int j = 0; j < 8; j++) {
        hh[j] = __float2bfloat16(vv[j]);
        ll[j] = __float2bfloat16(vv[j] - __bfloat162float(hh[j]));
    }
    *(uint2*)&Yh[o + sb * 4]      = *(uint2*)&hh[0];
    *(uint2*)&Yh[o + 32 + sb * 4] = *(uint2*)&hh[4];
    *(uint2*)&Yl[o + sb * 4]      = *(uint2*)&ll[0];
    *(uint2*)&Yl[o + 32 + sb * 4] = *(uint2*)&ll[4];
}

// ---------------------------------------------------------------------------
// Launch
// ---------------------------------------------------------------------------
extern "C" void kernel_launch(void* const* d_in, const int* in_sizes, int n_in,
                              void* d_out, int out_size)
{
    const int*   idx   = (const int*)  d_in[0];
    const float* tok   = (const float*)d_in[1];
    const float* pos   = (const float*)d_in[2];
    const float* ln1w  = (const float*)d_in[3];
    const float* ln1b  = (const float*)d_in[4];
    const float* Wq    = (const float*)d_in[5];
    const float* bq    = (const float*)d_in[6];
    const float* Wk    = (const float*)d_in[7];
    const float* bk    = (const float*)d_in[8];
    const float* Wv    = (const float*)d_in[9];
    const float* bv    = (const float*)d_in[10];
    const float* Wo    = (const float*)d_in[11];
    const float* bo    = (const float*)d_in[12];
    const float* ln2w  = (const float*)d_in[13];
    const float* ln2b  = (const float*)d_in[14];
    const float* W1    = (const float*)d_in[15];
    const float* b1    = (const float*)d_in[16];
    const float* W2    = (const float*)d_in[17];
    const float* b2    = (const float*)d_in[18];
    const float* lnfw  = (const float*)d_in[19];
    const float* lnfb  = (const float*)d_in[20];
    const float* Whead = (const float*)d_in[21];
    float* out = (float*)d_out;

    float *x, *qkv, *bqkv;
    bf16 *h_hi, *h_lo, *y_hi, *y_lo, *h1_hi, *h1_lo;
    bf16 *wqkv_hi, *wqkv_lo, *wo_hi, *wo_lo, *w1_hi, *w1_lo, *w2_hi, *w2_lo, *wh_hi, *wh_lo;
    cudaGetSymbolAddress((void**)&x,     g_x);
    cudaGetSymbolAddress((void**)&qkv,   g_qkv);
    cudaGetSymbolAddress((void**)&bqkv,  g_bqkv);
    cudaGetSymbolAddress((void**)&h_hi,  g_h_hi);
    cudaGetSymbolAddress((void**)&h_lo,  g_h_lo);
    cudaGetSymbolAddress((void**)&y_hi,  g_y_hi);
    cudaGetSymbolAddress((void**)&y_lo,  g_y_lo);
    cudaGetSymbolAddress((void**)&h1_hi, g_h1_hi);
    cudaGetSymbolAddress((void**)&h1_lo, g_h1_lo);
    cudaGetSymbolAddress((void**)&wqkv_hi, g_wqkv_hi);
    cudaGetSymbolAddress((void**)&wqkv_lo, g_wqkv_lo);
    cudaGetSymbolAddress((void**)&wo_hi,   g_wo_hi);
    cudaGetSymbolAddress((void**)&wo_lo,   g_wo_lo);
    cudaGetSymbolAddress((void**)&w1_hi,   g_w1_hi);
    cudaGetSymbolAddress((void**)&w1_lo,   g_w1_lo);
    cudaGetSymbolAddress((void**)&w2_hi,   g_w2_hi);
    cudaGetSymbolAddress((void**)&w2_lo,   g_w2_lo);
    cudaGetSymbolAddress((void**)&wh_hi,   g_wh_hi);
    cudaGetSymbolAddress((void**)&wh_lo,   g_wh_lo);

    const int M = BB * TT;

    pack_all<<<4 * 768 + (VV / 64) * (CC / 64), 256>>>(
        Wq, Wk, Wv, Wo, W1, W2, Whead,
        wqkv_hi, wqkv_lo, wo_hi, wo_lo, w1_hi, w1_lo, w2_hi, w2_lo, wh_hi, wh_lo);
    pack_bqkv<<<(LL * 3 * CC + 255) / 256, 256>>>(bq, bk, bv, bqkv);
    embed_kernel<<<(M * CC / 4 + 255) / 256, 256>>>(idx, tok, pos, x);

    for (int l = 0; l < LL; l++) {
        const size_t bOff  = (size_t)l * CC;
        const size_t b1Off = (size_t)l * 4 * CC;

        ln_split<<<M, 128>>>(x, ln1w + bOff, ln1b + bOff, h_hi, h_lo);

        gemm_tc2<0, 4, 64><<<dim3(24, 16), 256>>>(
            h_hi, h_lo, wqkv_hi + (size_t)l*3*CC*CC, wqkv_lo + (size_t)l*3*CC*CC,
            bqkv + (size_t)l*3*CC, nullptr, qkv, nullptr, nullptr, M, 3 * CC, CC);

        attn_kernel<<<dim3(TT / 32, HH, BB), 256>>>(qkv, y_hi, y_lo);

        gemm_tc2<1, 2, 64><<<dim3(8, 32), 128>>>(
            y_hi, y_lo, wo_hi + (size_t)l*CC*CC, wo_lo + (size_t)l*CC*CC,
            bo + bOff, x, x, nullptr, nullptr, M, CC, CC);

        ln_split<<<M, 128>>>(x, ln2w + bOff, ln2b + bOff, h_hi, h_lo);

        gemm_tc2<2, 4, 64><<<dim3(32, 16), 256>>>(
            h_hi, h_lo, w1_hi + (size_t)l*4*CC*CC, w1_lo + (size_t)l*4*CC*CC,
            b1 + b1Off, nullptr, nullptr, h1_hi, h1_lo, M, 4 * CC, CC);

        gemm_tc2<1, 2, 64><<<dim3(8, 32), 128>>>(
            h1_hi, h1_lo, w2_hi + (size_t)l*4*CC*CC, w2_lo + (size_t)l*4*CC*CC,
            b2 + bOff, x, x, nullptr, nullptr, M, CC, 4 * CC);
    }

    ln_split<<<M, 128>>>(x, lnfw, lnfb, h_hi, h_lo);
    // Head GEMM: BN=128 tile for A-reuse (halves L2 A-traffic)
    gemm_tc2<0, 4, 128><<<dim3(VV / 128, 16), 256>>>(
        h_hi, h_lo, wh_hi, wh_lo, nullptr, nullptr, out, nullptr, nullptr, M, VV, CC);
}